// round 13
// baseline (speedup 1.0000x reference)
#include <cuda_runtime.h>
#include <cuda_bf16.h>
#include <math.h>
#include <stdint.h>

#define B_SZ   2
#define SEQ    2048
#define DMODEL 1024
#define DINNER 2048
#define DSTATE 16
#define DTRANK 64
#define DCONV  4
#define MROWS  (B_SZ*SEQ)   // 4096
#define XDBL_W 96
#define KSPLIT 4

// ---------------- scratch ----------------
__device__ float g_xz   [(size_t)MROWS * 2 * DINNER];
__device__ float g_xc   [(size_t)MROWS * DINNER];
__device__ float g_xdblp[(size_t)KSPLIT * MROWS * XDBL_W];
__device__ float g_dt   [(size_t)MROWS * DINNER];

// channel-major transposed arrays for the scan
__device__ float g_dtT  [(size_t)MROWS * DINNER];
__device__ float g_xcT  [(size_t)MROWS * DINNER];
__device__ float g_zsT  [(size_t)MROWS * DINNER];
__device__ float g_BT   [(size_t)B_SZ * DSTATE * SEQ];
__device__ float g_CT   [(size_t)B_SZ * DSTATE * SEQ];

// bf16 hi/lo splits
__device__ __nv_bfloat16 g_xh  [(size_t)MROWS * DMODEL];
__device__ __nv_bfloat16 g_xl  [(size_t)MROWS * DMODEL];
__device__ __nv_bfloat16 g_wih [(size_t)(2*DINNER) * DMODEL];
__device__ __nv_bfloat16 g_wil [(size_t)(2*DINNER) * DMODEL];
__device__ __nv_bfloat16 g_yh  [(size_t)MROWS * DINNER];
__device__ __nv_bfloat16 g_yl  [(size_t)MROWS * DINNER];
__device__ __nv_bfloat16 g_woh [(size_t)DMODEL * DINNER];
__device__ __nv_bfloat16 g_wol [(size_t)DMODEL * DINNER];
__device__ __nv_bfloat16 g_x64h[(size_t)MROWS * DTRANK];
__device__ __nv_bfloat16 g_x64l[(size_t)MROWS * DTRANK];
__device__ __nv_bfloat16 g_dwh [(size_t)DINNER * DTRANK];
__device__ __nv_bfloat16 g_dwl [(size_t)DINNER * DTRANK];

// ======================= helpers =======================
__device__ __forceinline__ uint32_t smem_to_u32(const void* p) {
    uint32_t a;
    asm("{ .reg .u64 t; cvta.to.shared.u64 t, %1; cvt.u32.u64 %0, t; }"
        : "=r"(a) : "l"(p));
    return a;
}

#define LDM_X4(r, addr) \
    asm volatile("ldmatrix.sync.aligned.m8n8.x4.shared.b16 {%0,%1,%2,%3}, [%4];" \
        : "=r"((r)[0]), "=r"((r)[1]), "=r"((r)[2]), "=r"((r)[3]) : "r"(addr))

#define MMA16816(c, a, b0, b1) \
    asm volatile("mma.sync.aligned.m16n8k16.row.col.f32.bf16.bf16.f32 " \
        "{%0,%1,%2,%3}, {%4,%5,%6,%7}, {%8,%9}, {%0,%1,%2,%3};" \
        : "+f"((c)[0]), "+f"((c)[1]), "+f"((c)[2]), "+f"((c)[3]) \
        : "r"((a)[0]), "r"((a)[1]), "r"((a)[2]), "r"((a)[3]), "r"(b0), "r"(b1))

#define CP_ASYNC16(saddr, gptr) \
    asm volatile("cp.async.cg.shared.global [%0], [%1], 16;" \
        :: "r"(saddr), "l"(gptr) : "memory")
#define CP_COMMIT() asm volatile("cp.async.commit_group;" ::: "memory")
#define CP_WAIT(n)  asm volatile("cp.async.wait_group %0;" :: "n"(n) : "memory")

// ====== split-bf16 HMMA GEMM (R7 config): 128x128 tile, 256 thr, 64x32 warps ==
// EPI: 0 = none, 1 = softplus(v + bias[col])
#define LDSH   40
#define STG_H  (128*LDSH)
#define STAGE_H (4*STG_H)
#define HMMA_SMEM (2*STAGE_H*2)      // 81920 bytes -> 2 CTAs/SM

template<int EPI>
__global__ void __launch_bounds__(256, 1)
hmma_gemm(const __nv_bfloat16* __restrict__ Ah, const __nv_bfloat16* __restrict__ Al,
          const __nv_bfloat16* __restrict__ Bh, const __nv_bfloat16* __restrict__ Bl,
          float* __restrict__ C, const float* __restrict__ bias, int K, int N)
{
    extern __shared__ __nv_bfloat16 sm[];
    const int tid  = threadIdx.x;
    const int lane = tid & 31;
    const int w    = tid >> 5;
    const int wm   = w >> 2;          // 0..1
    const int wn   = w & 3;           // 0..3
    const int row0 = blockIdx.y * 128;
    const int col0 = blockIdx.x * 128;
    const uint32_t sbase = smem_to_u32(sm);

    const int nc = K >> 5;

    auto load_stage = [&](int c, int s) {
        #pragma unroll
        for (int j = 0; j < 2; j++) {
            int i = tid + j * 256;
            int r = i >> 2, q = i & 3;
            size_t gA = (size_t)(row0 + r) * K + c * 32 + q * 8;
            size_t gB = (size_t)(col0 + r) * K + c * 32 + q * 8;
            uint32_t sa = sbase + (uint32_t)(s * STAGE_H + r * LDSH + q * 8) * 2;
            CP_ASYNC16(sa,                (const void*)(Ah + gA));
            CP_ASYNC16(sa + STG_H*2,      (const void*)(Al + gA));
            CP_ASYNC16(sa + 2*STG_H*2,    (const void*)(Bh + gB));
            CP_ASYNC16(sa + 3*STG_H*2,    (const void*)(Bl + gB));
        }
    };

    float acc[4][4][4];
    #pragma unroll
    for (int mi = 0; mi < 4; mi++)
        #pragma unroll
        for (int nj = 0; nj < 4; nj++)
            #pragma unroll
            for (int q = 0; q < 4; q++) acc[mi][nj][q] = 0.f;

    load_stage(0, 0);
    CP_COMMIT();

    for (int c = 0; c < nc; c++) {
        int s = c & 1;
        if (c + 1 < nc) {
            load_stage(c + 1, (c + 1) & 1);
            CP_COMMIT();
            CP_WAIT(1);
        } else {
            CP_WAIT(0);
        }
        __syncthreads();

        #pragma unroll
        for (int ks = 0; ks < 2; ks++) {
            uint32_t ah[4][4], al[4][4];
            #pragma unroll
            for (int mi = 0; mi < 4; mi++) {
                uint32_t off = (uint32_t)(s * STAGE_H
                             + (wm*64 + mi*16 + (lane & 15)) * LDSH
                             + ks*16 + (lane >> 4) * 8);
                uint32_t ad = sbase + off * 2;
                LDM_X4(ah[mi], ad);
                LDM_X4(al[mi], ad + STG_H*2);
            }
            uint32_t bh[2][4], bl[2][4];
            #pragma unroll
            for (int np = 0; np < 2; np++) {
                uint32_t off = (uint32_t)(s * STAGE_H + 2*STG_H
                             + (wn*32 + np*16 + (lane & 7) + ((lane >> 3) & 1) * 8) * LDSH
                             + ks*16 + (lane >> 4) * 8);
                uint32_t bd = sbase + off * 2;
                LDM_X4(bh[np], bd);
                LDM_X4(bl[np], bd + STG_H*2);
            }
            #pragma unroll
            for (int mi = 0; mi < 4; mi++)
                #pragma unroll
                for (int np = 0; np < 2; np++)
                    #pragma unroll
                    for (int sub = 0; sub < 2; sub++) {
                        int nj = np * 2 + sub;
                        MMA16816(acc[mi][nj], ah[mi], bh[np][sub], bh[np][sub + 2]);
                        MMA16816(acc[mi][nj], ah[mi], bl[np][sub], bl[np][sub + 2]);
                        MMA16816(acc[mi][nj], al[mi], bh[np][sub], bh[np][sub + 2]);
                    }
        }
        __syncthreads();
    }

    #pragma unroll
    for (int mi = 0; mi < 4; mi++)
        #pragma unroll
        for (int nj = 0; nj < 4; nj++) {
            int r  = row0 + wm*64 + mi*16 + (lane >> 2);
            int cc = col0 + wn*32 + nj*8 + (lane & 3) * 2;
            float v0 = acc[mi][nj][0], v1 = acc[mi][nj][1];
            float v2 = acc[mi][nj][2], v3 = acc[mi][nj][3];
            if (EPI == 1) {
                float b0 = bias[cc], b1 = bias[cc + 1];
                v0 += b0; v1 += b1; v2 += b0; v3 += b1;
                v0 = (v0 > 20.f) ? v0 : log1pf(__expf(v0));
                v1 = (v1 > 20.f) ? v1 : log1pf(__expf(v1));
                v2 = (v2 > 20.f) ? v2 : log1pf(__expf(v2));
                v3 = (v3 > 20.f) ? v3 : log1pf(__expf(v3));
            }
            *(float2*)(C + (size_t)r * N + cc)       = make_float2(v0, v1);
            *(float2*)(C + (size_t)(r + 8) * N + cc) = make_float2(v2, v3);
        }
}

// ---------------- fused fp32 -> bf16 hi/lo split for all 4 inputs ----------------
#define SPLIT_N0 (MROWS*DMODEL)            // x:          4194304
#define SPLIT_N1 (2*DINNER*DMODEL)         // in_proj_w:  4194304
#define SPLIT_N2 (DMODEL*DINNER)           // out_proj_w: 2097152
#define SPLIT_N3 (DINNER*DTRANK)           // dt_proj_w:   131072
#define SPLIT_TOT (SPLIT_N0+SPLIT_N1+SPLIT_N2+SPLIT_N3)

__global__ void split_all_kernel(const float* __restrict__ s0,
                                 const float* __restrict__ s1,
                                 const float* __restrict__ s2,
                                 const float* __restrict__ s3)
{
    int i = blockIdx.x * blockDim.x + threadIdx.x;
    if (i >= SPLIT_TOT) return;
    const float* src; __nv_bfloat16 *hi, *lo; int o;
    if (i < SPLIT_N0)                       { src = s0; hi = g_xh;  lo = g_xl;  o = i; }
    else if (i < SPLIT_N0+SPLIT_N1)         { src = s1; hi = g_wih; lo = g_wil; o = i - SPLIT_N0; }
    else if (i < SPLIT_N0+SPLIT_N1+SPLIT_N2){ src = s2; hi = g_woh; lo = g_wol; o = i - SPLIT_N0 - SPLIT_N1; }
    else                                    { src = s3; hi = g_dwh; lo = g_dwl; o = i - SPLIT_N0 - SPLIT_N1 - SPLIT_N2; }
    float v = src[o];
    __nv_bfloat16 h = __float2bfloat16(v);
    hi[o] = h;
    lo[o] = __float2bfloat16(v - __bfloat162float(h));
}

// ---------------- split-K SIMT GEMM for x_proj ------
__global__ void __launch_bounds__(256, 2) sgemm_splitk(
    const float* __restrict__ A, const float* __restrict__ Bw,
    float* __restrict__ Cpart, int M, int N, int Kc, int lda, int ldb)
{
    __shared__ float As[8][128];
    __shared__ float Bs[8][128];
    int tid  = threadIdx.x;
    int row0 = blockIdx.y * 128;
    int col0 = blockIdx.x * 128;
    int z    = blockIdx.z;
    int tx = tid & 15, ty = tid >> 4;
    int ldRow = tid >> 1, ldCol = (tid & 1) * 4;

    float acc[8][8];
    #pragma unroll
    for (int i = 0; i < 8; i++)
        #pragma unroll
        for (int j = 0; j < 8; j++) acc[i][j] = 0.f;

    const float* Aptr = A + (size_t)(row0 + ldRow) * lda + z * Kc + ldCol;
    bool bValid = (col0 + ldRow) < N;
    const float* Bptr = Bw + (size_t)(col0 + ldRow) * ldb + z * Kc + ldCol;

    for (int k0 = 0; k0 < Kc; k0 += 8) {
        float4 av = *(const float4*)(Aptr + k0);
        float4 bv = bValid ? *(const float4*)(Bptr + k0) : make_float4(0.f,0.f,0.f,0.f);
        As[ldCol+0][ldRow] = av.x; As[ldCol+1][ldRow] = av.y;
        As[ldCol+2][ldRow] = av.z; As[ldCol+3][ldRow] = av.w;
        Bs[ldCol+0][ldRow] = bv.x; Bs[ldCol+1][ldRow] = bv.y;
        Bs[ldCol+2][ldRow] = bv.z; Bs[ldCol+3][ldRow] = bv.w;
        __syncthreads();
        #pragma unroll
        for (int kk = 0; kk < 8; kk++) {
            float a[8], b[8];
            *(float4*)(a)     = *(const float4*)&As[kk][ty*8];
            *(float4*)(a + 4) = *(const float4*)&As[kk][ty*8+4];
            *(float4*)(b)     = *(const float4*)&Bs[kk][tx*8];
            *(float4*)(b + 4) = *(const float4*)&Bs[kk][tx*8+4];
            #pragma unroll
            for (int i = 0; i < 8; i++)
                #pragma unroll
                for (int j = 0; j < 8; j++)
                    acc[i][j] = fmaf(a[i], b[j], acc[i][j]);
        }
        __syncthreads();
    }
    float* Cz = Cpart + (size_t)z * M * N;
    #pragma unroll
    for (int i = 0; i < 8; i++) {
        int r = row0 + ty*8 + i;
        #pragma unroll
        for (int j = 0; j < 8; j++) {
            int c = col0 + tx*8 + j;
            if (c < N) Cz[(size_t)r * N + c] = acc[i][j];
        }
    }
}

// reduce split-K partials; dt-rank cols -> packed bf16 hi/lo, B/C -> transposed
__global__ void reduce_splitk_T(const float* __restrict__ parts)
{
    const int total = MROWS * XDBL_W;
    int i = blockIdx.x * blockDim.x + threadIdx.x;
    if (i >= total) return;
    float v = parts[i] + parts[i + (size_t)total] +
              parts[i + 2*(size_t)total] + parts[i + 3*(size_t)total];
    int m = i / XDBL_W;
    int c = i - m * XDBL_W;
    if (c < DTRANK) {
        __nv_bfloat16 h = __float2bfloat16(v);
        g_x64h[m * DTRANK + c] = h;
        g_x64l[m * DTRANK + c] = __float2bfloat16(v - __bfloat162float(h));
    } else {
        int b = m >> 11, t = m & (SEQ - 1);
        int cc = c - DTRANK;          // 0..31
        if (cc < DSTATE) g_BT[(size_t)(b*DSTATE + cc) * SEQ + t] = v;
        else             g_CT[(size_t)(b*DSTATE + cc - DSTATE) * SEQ + t] = v;
    }
}

// ---------------- causal depthwise conv (k=4) + SiLU ----------------
__global__ void conv_silu_kernel(const float* __restrict__ conv_w,
                                 const float* __restrict__ conv_b)
{
    int idx = blockIdx.x * blockDim.x + threadIdx.x;
    int d = idx & (DINNER - 1);
    int m = idx >> 11;
    int l = m & (SEQ - 1);
    int b = m >> 11;
    float s = conv_b[d];
    #pragma unroll
    for (int j = 0; j < DCONV; j++) {
        int li = l - (DCONV - 1) + j;
        if (li >= 0)
            s = fmaf(conv_w[d * DCONV + j],
                     g_xz[(size_t)(b * SEQ + li) * (2 * DINNER) + d], s);
    }
    g_xc[idx] = s / (1.f + __expf(-s));
}

// ---------------- batched tiled transpose: dt->dtT, xc->xcT, silu(z)->zsT ----
__global__ void __launch_bounds__(256) transpose3_kernel()
{
    __shared__ float tile[32][33];
    int zsel = blockIdx.z;
    int b  = blockIdx.y >> 6;
    int t0 = (blockIdx.y & 63) << 5;
    int d0 = blockIdx.x << 5;
    int tx = threadIdx.x & 31, ty = threadIdx.x >> 5;

    const float* src; int stride;
    if (zsel == 0)      { src = g_dt;          stride = DINNER;   }
    else if (zsel == 1) { src = g_xc;          stride = DINNER;   }
    else                { src = g_xz + DINNER; stride = 2*DINNER; }

    #pragma unroll
    for (int k = 0; k < 32; k += 8) {
        float v = src[(size_t)(b*SEQ + t0 + ty + k) * stride + d0 + tx];
        if (zsel == 2) v = v / (1.f + __expf(-v));
        tile[ty + k][tx] = v;
    }
    __syncthreads();
    float* dst = (zsel == 0) ? g_dtT : (zsel == 1) ? g_xcT : g_zsT;
    #pragma unroll
    for (int k = 0; k < 32; k += 8)
        dst[(size_t)(b*DINNER + d0 + ty + k) * SEQ + t0 + tx] = tile[tx][ty + k];
}

// ---------------- selective scan v5: smem B/C tiles, packed stores ----------
#define UNR2 16
#define T_TILE 128
#define SPAD 132
__global__ void __launch_bounds__(256) scan_kernel(const float* __restrict__ A_log,
                                                   const float* __restrict__ Dp)
{
    __shared__ float sB[DSTATE][SPAD];
    __shared__ float sC[DSTATE][SPAD];

    int tid  = threadIdx.x;
    int lane = tid & 31;
    int warp = tid >> 5;
    int c2 = lane >> 4;
    int n  = lane & 15;
    int ch = blockIdx.x * 16 + warp * 2 + c2;
    int b  = ch >> 11;
    int d  = ch & (DINNER - 1);
    int d0 = d & ~1;

    float Ac = -__expf(__ldg(A_log + d * DSTATE + n));
    float Dd = Dp[d];
    float h  = 0.f;

    const float* dtT = g_dtT + (size_t)ch * SEQ;
    const float* xT  = g_xcT + (size_t)ch * SEQ;
    const float* zT  = g_zsT + (size_t)ch * SEQ;
    const float* BTb = g_BT  + (size_t)b * DSTATE * SEQ;
    const float* CTb = g_CT  + (size_t)b * DSTATE * SEQ;
    int srcbase = c2 << 4;

    int ldr = tid >> 5;
    int ldc = (tid & 31) * 4;

    for (int tb = 0; tb < SEQ; tb += T_TILE) {
        __syncthreads();
        #pragma unroll
        for (int rr = 0; rr < 2; rr++) {
            int r = ldr + rr * 8;
            float4 bv = *(const float4*)(BTb + (size_t)r * SEQ + tb + ldc);
            float4 cv = *(const float4*)(CTb + (size_t)r * SEQ + tb + ldc);
            *(float4*)&sB[r][ldc] = bv;
            *(float4*)&sC[r][ldc] = cv;
        }
        __syncthreads();

        for (int tt = 0; tt < T_TILE; tt += UNR2) {
            int t0 = tb + tt;
            float dt_l = __ldg(dtT + t0 + n);
            float x_l  = __ldg(xT  + t0 + n);
            float z_l  = __ldg(zT  + t0 + n);
            float pre_l = dt_l * x_l;

            float Bn[UNR2], Cn[UNR2];
            #pragma unroll
            for (int q = 0; q < UNR2; q += 4) {
                float4 bq = *(const float4*)&sB[n][tt + q];
                float4 cq = *(const float4*)&sC[n][tt + q];
                Bn[q] = bq.x; Bn[q+1] = bq.y; Bn[q+2] = bq.z; Bn[q+3] = bq.w;
                Cn[q] = cq.x; Cn[q+1] = cq.y; Cn[q+2] = cq.z; Cn[q+3] = cq.w;
            }

            float dA[UNR2];
            #pragma unroll
            for (int u = 0; u < UNR2; u++) {
                float dtu  = __shfl_sync(0xffffffffu, dt_l,  srcbase + u);
                float preu = __shfl_sync(0xffffffffu, pre_l, srcbase + u);
                Bn[u] = preu * Bn[u];
                dA[u] = __expf(dtu * Ac);
            }

            float p[UNR2];
            #pragma unroll
            for (int u = 0; u < UNR2; u++) {
                h = fmaf(dA[u], h, Bn[u]);
                p[u] = h * Cn[u];
            }

            // reduce-scatter: lane n ends with sum for timestep t0+n
            float q8[8];
            #pragma unroll
            for (int v = 0; v < 8; v++) {
                float keep = (n & 8) ? p[v + 8] : p[v];
                float send = (n & 8) ? p[v]     : p[v + 8];
                q8[v] = keep + __shfl_xor_sync(0xffffffffu, send, 8);
            }
            float q4[4];
            #pragma unroll
            for (int v = 0; v < 4; v++) {
                float keep = (n & 4) ? q8[v + 4] : q8[v];
                float send = (n & 4) ? q8[v]     : q8[v + 4];
                q4[v] = keep + __shfl_xor_sync(0xffffffffu, send, 4);
            }
            float q2[2];
            #pragma unroll
            for (int v = 0; v < 2; v++) {
                float keep = (n & 2) ? q4[v + 2] : q4[v];
                float send = (n & 2) ? q4[v]     : q4[v + 2];
                q2[v] = keep + __shfl_xor_sync(0xffffffffu, send, 2);
            }
            float keep = (n & 1) ? q2[1] : q2[0];
            float send = (n & 1) ? q2[0] : q2[1];
            float ps = keep + __shfl_xor_sync(0xffffffffu, send, 1);

            float yv = fmaf(Dd, x_l, ps) * z_l;
            float yvp = __shfl_xor_sync(0xffffffffu, yv, 16);
            if (c2 == 0) {
                __nv_bfloat16 h0 = __float2bfloat16(yv);
                __nv_bfloat16 h1 = __float2bfloat16(yvp);
                __nv_bfloat16 l0 = __float2bfloat16(yv  - __bfloat162float(h0));
                __nv_bfloat16 l1 = __float2bfloat16(yvp - __bfloat162float(h1));
                size_t m = (size_t)(b * SEQ + t0 + n);
                *(__nv_bfloat162*)(g_yh + m * DINNER + d0) = __halves2bfloat162(h0, h1);
                *(__nv_bfloat162*)(g_yl + m * DINNER + d0) = __halves2bfloat162(l0, l1);
            }
        }
    }
}

// ---------------- launch ----------------
extern "C" void kernel_launch(void* const* d_in, const int* in_sizes, int n_in,
                              void* d_out, int out_size)
{
    const float* x          = (const float*)d_in[0];
    const float* in_proj_w  = (const float*)d_in[1];
    const float* conv_w     = (const float*)d_in[2];
    const float* conv_b     = (const float*)d_in[3];
    const float* A_log      = (const float*)d_in[4];
    const float* Dp         = (const float*)d_in[5];
    const float* x_proj_w   = (const float*)d_in[6];
    const float* dt_proj_w  = (const float*)d_in[7];
    const float* dt_proj_b  = (const float*)d_in[8];
    const float* out_proj_w = (const float*)d_in[9];
    float*       out        = (float*)d_out;

    float *xz, *xc, *xdblp, *dt;
    __nv_bfloat16 *xh, *xl, *wih, *wil, *yh, *yl, *woh, *wol, *dwh, *dwl, *x64h, *x64l;
    cudaGetSymbolAddress((void**)&xz,    g_xz);
    cudaGetSymbolAddress((void**)&xc,    g_xc);
    cudaGetSymbolAddress((void**)&xdblp, g_xdblp);
    cudaGetSymbolAddress((void**)&dt,    g_dt);
    cudaGetSymbolAddress((void**)&xh,   g_xh);
    cudaGetSymbolAddress((void**)&xl,   g_xl);
    cudaGetSymbolAddress((void**)&wih,  g_wih);
    cudaGetSymbolAddress((void**)&wil,  g_wil);
    cudaGetSymbolAddress((void**)&yh,   g_yh);
    cudaGetSymbolAddress((void**)&yl,   g_yl);
    cudaGetSymbolAddress((void**)&woh,  g_woh);
    cudaGetSymbolAddress((void**)&wol,  g_wol);
    cudaGetSymbolAddress((void**)&dwh,  g_dwh);
    cudaGetSymbolAddress((void**)&dwl,  g_dwl);
    cudaGetSymbolAddress((void**)&x64h, g_x64h);
    cudaGetSymbolAddress((void**)&x64l, g_x64l);

    cudaFuncSetAttribute(hmma_gemm<0>, cudaFuncAttributeMaxDynamicSharedMemorySize,
                         HMMA_SMEM);
    cudaFuncSetAttribute(hmma_gemm<1>, cudaFuncAttributeMaxDynamicSharedMemorySize,
                         HMMA_SMEM);

    // 0) fused bf16 hi/lo splits of all 4 fp32 inputs
    split_all_kernel<<<(SPLIT_TOT + 255)/256, 256>>>(x, in_proj_w, out_proj_w, dt_proj_w);

    // 1) xz = x @ in_proj_w^T  [4096,4096] K=1024
    hmma_gemm<0><<<dim3(32, 32), 256, HMMA_SMEM>>>(xh, xl, wih, wil, xz, nullptr,
                                                   DMODEL, 2*DINNER);

    // 2) causal depthwise conv + silu
    conv_silu_kernel<<<(MROWS * DINNER) / 256, 256>>>(conv_w, conv_b);

    // 3) x_dbl = xc @ x_proj_w^T — split-K x4 + routed reduce (B,C transposed;
    //    dt-rank columns written directly as packed bf16 hi/lo)
    sgemm_splitk<<<dim3(1, 32, KSPLIT), 256>>>(xc, x_proj_w, xdblp,
                                               MROWS, XDBL_W, DINNER/KSPLIT,
                                               DINNER, DINNER);
    reduce_splitk_T<<<(MROWS*XDBL_W + 255)/256, 256>>>(xdblp);

    // 4) dt = softplus(xdbl64 @ dt_proj_w^T + b)  [4096,2048] K=64 — HMMA
    hmma_gemm<1><<<dim3(16, 32), 256, HMMA_SMEM>>>(x64h, x64l, dwh, dwl, dt, dt_proj_b,
                                                   DTRANK, DINNER);

    // 4b) transposes: dt->dtT, xc->xcT, silu(z)->zsT
    transpose3_kernel<<<dim3(64, 128, 3), 256>>>();

    // 5) selective scan v5
    scan_kernel<<<256, 256>>>(A_log, Dp);

    // 6) out = y @ out_proj_w^T  [4096,1024] K=2048
    hmma_gemm<0><<<dim3(8, 32), 256, HMMA_SMEM>>>(yh, yl, woh, wol, out, nullptr,
                                                  DINNER, DMODEL);
}

// round 14
// speedup vs baseline: 1.5139x; 1.5139x over previous
#include <cuda_runtime.h>
#include <cuda_bf16.h>
#include <math.h>
#include <stdint.h>

#define B_SZ   2
#define SEQ    2048
#define DMODEL 1024
#define DINNER 2048
#define DSTATE 16
#define DTRANK 64
#define DCONV  4
#define MROWS  (B_SZ*SEQ)   // 4096
#define XDBL_W 96
#define KSPLIT 4

// ---------------- scratch ----------------
__device__ float g_xz   [(size_t)MROWS * 2 * DINNER];
__device__ float g_xc   [(size_t)MROWS * DINNER];
__device__ float g_xdbl [(size_t)MROWS * XDBL_W];
__device__ float g_xdblp[(size_t)KSPLIT * MROWS * XDBL_W];
__device__ float g_dt   [(size_t)MROWS * DINNER];

// channel-major transposed arrays for the scan
__device__ float g_dtT  [(size_t)MROWS * DINNER];
__device__ float g_xcT  [(size_t)MROWS * DINNER];
__device__ float g_zsT  [(size_t)MROWS * DINNER];
__device__ float g_BT   [(size_t)B_SZ * DSTATE * SEQ];
__device__ float g_CT   [(size_t)B_SZ * DSTATE * SEQ];

// bf16 hi/lo splits
__device__ __nv_bfloat16 g_xh  [(size_t)MROWS * DMODEL];
__device__ __nv_bfloat16 g_xl  [(size_t)MROWS * DMODEL];
__device__ __nv_bfloat16 g_wih [(size_t)(2*DINNER) * DMODEL];
__device__ __nv_bfloat16 g_wil [(size_t)(2*DINNER) * DMODEL];
__device__ __nv_bfloat16 g_yh  [(size_t)MROWS * DINNER];
__device__ __nv_bfloat16 g_yl  [(size_t)MROWS * DINNER];
__device__ __nv_bfloat16 g_woh [(size_t)DMODEL * DINNER];
__device__ __nv_bfloat16 g_wol [(size_t)DMODEL * DINNER];
__device__ __nv_bfloat16 g_x64h[(size_t)MROWS * DTRANK];
__device__ __nv_bfloat16 g_x64l[(size_t)MROWS * DTRANK];
__device__ __nv_bfloat16 g_dwh [(size_t)DINNER * DTRANK];
__device__ __nv_bfloat16 g_dwl [(size_t)DINNER * DTRANK];

// ======================= helpers =======================
__device__ __forceinline__ uint32_t smem_to_u32(const void* p) {
    uint32_t a;
    asm("{ .reg .u64 t; cvta.to.shared.u64 t, %1; cvt.u32.u64 %0, t; }"
        : "=r"(a) : "l"(p));
    return a;
}

#define LDM_X4(r, addr) \
    asm volatile("ldmatrix.sync.aligned.m8n8.x4.shared.b16 {%0,%1,%2,%3}, [%4];" \
        : "=r"((r)[0]), "=r"((r)[1]), "=r"((r)[2]), "=r"((r)[3]) : "r"(addr))

#define MMA16816(c, a, b0, b1) \
    asm volatile("mma.sync.aligned.m16n8k16.row.col.f32.bf16.bf16.f32 " \
        "{%0,%1,%2,%3}, {%4,%5,%6,%7}, {%8,%9}, {%0,%1,%2,%3};" \
        : "+f"((c)[0]), "+f"((c)[1]), "+f"((c)[2]), "+f"((c)[3]) \
        : "r"((a)[0]), "r"((a)[1]), "r"((a)[2]), "r"((a)[3]), "r"(b0), "r"(b1))

#define CP_ASYNC16(saddr, gptr) \
    asm volatile("cp.async.cg.shared.global [%0], [%1], 16;" \
        :: "r"(saddr), "l"(gptr) : "memory")
#define CP_COMMIT() asm volatile("cp.async.commit_group;" ::: "memory")
#define CP_WAIT(n)  asm volatile("cp.async.wait_group %0;" :: "n"(n) : "memory")

// ====== split-bf16 HMMA GEMM (R7 config): 128x128 tile, 256 thr, 64x32 warps ==
// EPI: 0 = none, 1 = softplus(v + bias[col])
#define LDSH   40
#define STG_H  (128*LDSH)
#define STAGE_H (4*STG_H)
#define HMMA_SMEM (2*STAGE_H*2)      // 81920 bytes -> 2 CTAs/SM

template<int EPI>
__global__ void __launch_bounds__(256, 1)
hmma_gemm(const __nv_bfloat16* __restrict__ Ah, const __nv_bfloat16* __restrict__ Al,
          const __nv_bfloat16* __restrict__ Bh, const __nv_bfloat16* __restrict__ Bl,
          float* __restrict__ C, const float* __restrict__ bias, int K, int N)
{
    extern __shared__ __nv_bfloat16 sm[];
    const int tid  = threadIdx.x;
    const int lane = tid & 31;
    const int w    = tid >> 5;
    const int wm   = w >> 2;          // 0..1
    const int wn   = w & 3;           // 0..3
    const int row0 = blockIdx.y * 128;
    const int col0 = blockIdx.x * 128;
    const uint32_t sbase = smem_to_u32(sm);

    const int nc = K >> 5;

    auto load_stage = [&](int c, int s) {
        #pragma unroll
        for (int j = 0; j < 2; j++) {
            int i = tid + j * 256;
            int r = i >> 2, q = i & 3;
            size_t gA = (size_t)(row0 + r) * K + c * 32 + q * 8;
            size_t gB = (size_t)(col0 + r) * K + c * 32 + q * 8;
            uint32_t sa = sbase + (uint32_t)(s * STAGE_H + r * LDSH + q * 8) * 2;
            CP_ASYNC16(sa,                (const void*)(Ah + gA));
            CP_ASYNC16(sa + STG_H*2,      (const void*)(Al + gA));
            CP_ASYNC16(sa + 2*STG_H*2,    (const void*)(Bh + gB));
            CP_ASYNC16(sa + 3*STG_H*2,    (const void*)(Bl + gB));
        }
    };

    float acc[4][4][4];
    #pragma unroll
    for (int mi = 0; mi < 4; mi++)
        #pragma unroll
        for (int nj = 0; nj < 4; nj++)
            #pragma unroll
            for (int q = 0; q < 4; q++) acc[mi][nj][q] = 0.f;

    load_stage(0, 0);
    CP_COMMIT();

    for (int c = 0; c < nc; c++) {
        int s = c & 1;
        if (c + 1 < nc) {
            load_stage(c + 1, (c + 1) & 1);
            CP_COMMIT();
            CP_WAIT(1);
        } else {
            CP_WAIT(0);
        }
        __syncthreads();

        #pragma unroll
        for (int ks = 0; ks < 2; ks++) {
            uint32_t ah[4][4], al[4][4];
            #pragma unroll
            for (int mi = 0; mi < 4; mi++) {
                uint32_t off = (uint32_t)(s * STAGE_H
                             + (wm*64 + mi*16 + (lane & 15)) * LDSH
                             + ks*16 + (lane >> 4) * 8);
                uint32_t ad = sbase + off * 2;
                LDM_X4(ah[mi], ad);
                LDM_X4(al[mi], ad + STG_H*2);
            }
            uint32_t bh[2][4], bl[2][4];
            #pragma unroll
            for (int np = 0; np < 2; np++) {
                uint32_t off = (uint32_t)(s * STAGE_H + 2*STG_H
                             + (wn*32 + np*16 + (lane & 7) + ((lane >> 3) & 1) * 8) * LDSH
                             + ks*16 + (lane >> 4) * 8);
                uint32_t bd = sbase + off * 2;
                LDM_X4(bh[np], bd);
                LDM_X4(bl[np], bd + STG_H*2);
            }
            #pragma unroll
            for (int mi = 0; mi < 4; mi++)
                #pragma unroll
                for (int np = 0; np < 2; np++)
                    #pragma unroll
                    for (int sub = 0; sub < 2; sub++) {
                        int nj = np * 2 + sub;
                        MMA16816(acc[mi][nj], ah[mi], bh[np][sub], bh[np][sub + 2]);
                        MMA16816(acc[mi][nj], ah[mi], bl[np][sub], bl[np][sub + 2]);
                        MMA16816(acc[mi][nj], al[mi], bh[np][sub], bh[np][sub + 2]);
                    }
        }
        __syncthreads();
    }

    #pragma unroll
    for (int mi = 0; mi < 4; mi++)
        #pragma unroll
        for (int nj = 0; nj < 4; nj++) {
            int r  = row0 + wm*64 + mi*16 + (lane >> 2);
            int cc = col0 + wn*32 + nj*8 + (lane & 3) * 2;
            float v0 = acc[mi][nj][0], v1 = acc[mi][nj][1];
            float v2 = acc[mi][nj][2], v3 = acc[mi][nj][3];
            if (EPI == 1) {
                float b0 = bias[cc], b1 = bias[cc + 1];
                v0 += b0; v1 += b1; v2 += b0; v3 += b1;
                v0 = (v0 > 20.f) ? v0 : log1pf(__expf(v0));
                v1 = (v1 > 20.f) ? v1 : log1pf(__expf(v1));
                v2 = (v2 > 20.f) ? v2 : log1pf(__expf(v2));
                v3 = (v3 > 20.f) ? v3 : log1pf(__expf(v3));
            }
            *(float2*)(C + (size_t)r * N + cc)       = make_float2(v0, v1);
            *(float2*)(C + (size_t)(r + 8) * N + cc) = make_float2(v2, v3);
        }
}

// ---------------- fp32 -> bf16 hi/lo split ----------------
__global__ void split_kernel(const float* __restrict__ src,
                             __nv_bfloat16* __restrict__ hi,
                             __nv_bfloat16* __restrict__ lo, int n)
{
    int i = blockIdx.x * blockDim.x + threadIdx.x;
    if (i < n) {
        float v = src[i];
        __nv_bfloat16 h = __float2bfloat16(v);
        hi[i] = h;
        lo[i] = __float2bfloat16(v - __bfloat162float(h));
    }
}

// strided split: xdbl[:, 0:64] -> packed [MROWS,64] hi/lo
__global__ void split_x64_kernel()
{
    int i = blockIdx.x * blockDim.x + threadIdx.x;
    if (i < MROWS * DTRANK) {
        int row = i >> 6, col = i & 63;
        float v = g_xdbl[row * XDBL_W + col];
        __nv_bfloat16 h = __float2bfloat16(v);
        g_x64h[i] = h;
        g_x64l[i] = __float2bfloat16(v - __bfloat162float(h));
    }
}

// ---------------- split-K SIMT GEMM for x_proj ------
__global__ void __launch_bounds__(256, 2) sgemm_splitk(
    const float* __restrict__ A, const float* __restrict__ Bw,
    float* __restrict__ Cpart, int M, int N, int Kc, int lda, int ldb)
{
    __shared__ float As[8][128];
    __shared__ float Bs[8][128];
    int tid  = threadIdx.x;
    int row0 = blockIdx.y * 128;
    int col0 = blockIdx.x * 128;
    int z    = blockIdx.z;
    int tx = tid & 15, ty = tid >> 4;
    int ldRow = tid >> 1, ldCol = (tid & 1) * 4;

    float acc[8][8];
    #pragma unroll
    for (int i = 0; i < 8; i++)
        #pragma unroll
        for (int j = 0; j < 8; j++) acc[i][j] = 0.f;

    const float* Aptr = A + (size_t)(row0 + ldRow) * lda + z * Kc + ldCol;
    bool bValid = (col0 + ldRow) < N;
    const float* Bptr = Bw + (size_t)(col0 + ldRow) * ldb + z * Kc + ldCol;

    for (int k0 = 0; k0 < Kc; k0 += 8) {
        float4 av = *(const float4*)(Aptr + k0);
        float4 bv = bValid ? *(const float4*)(Bptr + k0) : make_float4(0.f,0.f,0.f,0.f);
        As[ldCol+0][ldRow] = av.x; As[ldCol+1][ldRow] = av.y;
        As[ldCol+2][ldRow] = av.z; As[ldCol+3][ldRow] = av.w;
        Bs[ldCol+0][ldRow] = bv.x; Bs[ldCol+1][ldRow] = bv.y;
        Bs[ldCol+2][ldRow] = bv.z; Bs[ldCol+3][ldRow] = bv.w;
        __syncthreads();
        #pragma unroll
        for (int kk = 0; kk < 8; kk++) {
            float a[8], b[8];
            *(float4*)(a)     = *(const float4*)&As[kk][ty*8];
            *(float4*)(a + 4) = *(const float4*)&As[kk][ty*8+4];
            *(float4*)(b)     = *(const float4*)&Bs[kk][tx*8];
            *(float4*)(b + 4) = *(const float4*)&Bs[kk][tx*8+4];
            #pragma unroll
            for (int i = 0; i < 8; i++)
                #pragma unroll
                for (int j = 0; j < 8; j++)
                    acc[i][j] = fmaf(a[i], b[j], acc[i][j]);
        }
        __syncthreads();
    }
    float* Cz = Cpart + (size_t)z * M * N;
    #pragma unroll
    for (int i = 0; i < 8; i++) {
        int r = row0 + ty*8 + i;
        #pragma unroll
        for (int j = 0; j < 8; j++) {
            int c = col0 + tx*8 + j;
            if (c < N) Cz[(size_t)r * N + c] = acc[i][j];
        }
    }
}

// reduce split-K partials; route dt cols to xdbl, B/C cols to transposed arrays
__global__ void reduce_splitk_T(const float* __restrict__ parts)
{
    const int total = MROWS * XDBL_W;
    int i = blockIdx.x * blockDim.x + threadIdx.x;
    if (i >= total) return;
    float v = parts[i] + parts[i + (size_t)total] +
              parts[i + 2*(size_t)total] + parts[i + 3*(size_t)total];
    int m = i / XDBL_W;
    int c = i - m * XDBL_W;
    if (c < DTRANK) {
        g_xdbl[i] = v;
    } else {
        int b = m >> 11, t = m & (SEQ - 1);
        int cc = c - DTRANK;          // 0..31
        if (cc < DSTATE) g_BT[(size_t)(b*DSTATE + cc) * SEQ + t] = v;
        else             g_CT[(size_t)(b*DSTATE + cc - DSTATE) * SEQ + t] = v;
    }
}

// ---------------- causal depthwise conv (k=4) + SiLU ----------------
__global__ void conv_silu_kernel(const float* __restrict__ conv_w,
                                 const float* __restrict__ conv_b)
{
    int idx = blockIdx.x * blockDim.x + threadIdx.x;
    int d = idx & (DINNER - 1);
    int m = idx >> 11;
    int l = m & (SEQ - 1);
    int b = m >> 11;
    float s = conv_b[d];
    #pragma unroll
    for (int j = 0; j < DCONV; j++) {
        int li = l - (DCONV - 1) + j;
        if (li >= 0)
            s = fmaf(conv_w[d * DCONV + j],
                     g_xz[(size_t)(b * SEQ + li) * (2 * DINNER) + d], s);
    }
    g_xc[idx] = s / (1.f + __expf(-s));
}

// ---------------- batched tiled transpose: dt->dtT, xc->xcT, silu(z)->zsT ----
__global__ void __launch_bounds__(256) transpose3_kernel()
{
    __shared__ float tile[32][33];
    int zsel = blockIdx.z;
    int b  = blockIdx.y >> 6;
    int t0 = (blockIdx.y & 63) << 5;
    int d0 = blockIdx.x << 5;
    int tx = threadIdx.x & 31, ty = threadIdx.x >> 5;

    const float* src; int stride;
    if (zsel == 0)      { src = g_dt;          stride = DINNER;   }
    else if (zsel == 1) { src = g_xc;          stride = DINNER;   }
    else                { src = g_xz + DINNER; stride = 2*DINNER; }

    #pragma unroll
    for (int k = 0; k < 32; k += 8) {
        float v = src[(size_t)(b*SEQ + t0 + ty + k) * stride + d0 + tx];
        if (zsel == 2) v = v / (1.f + __expf(-v));
        tile[ty + k][tx] = v;
    }
    __syncthreads();
    float* dst = (zsel == 0) ? g_dtT : (zsel == 1) ? g_xcT : g_zsT;
    #pragma unroll
    for (int k = 0; k < 32; k += 8)
        dst[(size_t)(b*DINNER + d0 + ty + k) * SEQ + t0 + tx] = tile[tx][ty + k];
}

// ---------------- selective scan v5: smem B/C tiles, packed stores ----------
#define UNR2 16
#define T_TILE 128
#define SPAD 132
__global__ void __launch_bounds__(256) scan_kernel(const float* __restrict__ A_log,
                                                   const float* __restrict__ Dp)
{
    __shared__ float sB[DSTATE][SPAD];
    __shared__ float sC[DSTATE][SPAD];

    int tid  = threadIdx.x;
    int lane = tid & 31;
    int warp = tid >> 5;
    int c2 = lane >> 4;
    int n  = lane & 15;
    int ch = blockIdx.x * 16 + warp * 2 + c2;
    int b  = ch >> 11;
    int d  = ch & (DINNER - 1);
    int d0 = d & ~1;

    float Ac = -__expf(__ldg(A_log + d * DSTATE + n));
    float Dd = Dp[d];
    float h  = 0.f;

    const float* dtT = g_dtT + (size_t)ch * SEQ;
    const float* xT  = g_xcT + (size_t)ch * SEQ;
    const float* zT  = g_zsT + (size_t)ch * SEQ;
    const float* BTb = g_BT  + (size_t)b * DSTATE * SEQ;
    const float* CTb = g_CT  + (size_t)b * DSTATE * SEQ;
    int srcbase = c2 << 4;

    int ldr = tid >> 5;
    int ldc = (tid & 31) * 4;

    for (int tb = 0; tb < SEQ; tb += T_TILE) {
        __syncthreads();
        #pragma unroll
        for (int rr = 0; rr < 2; rr++) {
            int r = ldr + rr * 8;
            float4 bv = *(const float4*)(BTb + (size_t)r * SEQ + tb + ldc);
            float4 cv = *(const float4*)(CTb + (size_t)r * SEQ + tb + ldc);
            *(float4*)&sB[r][ldc] = bv;
            *(float4*)&sC[r][ldc] = cv;
        }
        __syncthreads();

        for (int tt = 0; tt < T_TILE; tt += UNR2) {
            int t0 = tb + tt;
            float dt_l = __ldg(dtT + t0 + n);
            float x_l  = __ldg(xT  + t0 + n);
            float z_l  = __ldg(zT  + t0 + n);
            float pre_l = dt_l * x_l;

            float Bn[UNR2], Cn[UNR2];
            #pragma unroll
            for (int q = 0; q < UNR2; q += 4) {
                float4 bq = *(const float4*)&sB[n][tt + q];
                float4 cq = *(const float4*)&sC[n][tt + q];
                Bn[q] = bq.x; Bn[q+1] = bq.y; Bn[q+2] = bq.z; Bn[q+3] = bq.w;
                Cn[q] = cq.x; Cn[q+1] = cq.y; Cn[q+2] = cq.z; Cn[q+3] = cq.w;
            }

            float dA[UNR2];
            #pragma unroll
            for (int u = 0; u < UNR2; u++) {
                float dtu  = __shfl_sync(0xffffffffu, dt_l,  srcbase + u);
                float preu = __shfl_sync(0xffffffffu, pre_l, srcbase + u);
                Bn[u] = preu * Bn[u];
                dA[u] = __expf(dtu * Ac);
            }

            float p[UNR2];
            #pragma unroll
            for (int u = 0; u < UNR2; u++) {
                h = fmaf(dA[u], h, Bn[u]);
                p[u] = h * Cn[u];
            }

            // reduce-scatter: lane n ends with sum for timestep t0+n
            float q8[8];
            #pragma unroll
            for (int v = 0; v < 8; v++) {
                float keep = (n & 8) ? p[v + 8] : p[v];
                float send = (n & 8) ? p[v]     : p[v + 8];
                q8[v] = keep + __shfl_xor_sync(0xffffffffu, send, 8);
            }
            float q4[4];
            #pragma unroll
            for (int v = 0; v < 4; v++) {
                float keep = (n & 4) ? q8[v + 4] : q8[v];
                float send = (n & 4) ? q8[v]     : q8[v + 4];
                q4[v] = keep + __shfl_xor_sync(0xffffffffu, send, 4);
            }
            float q2[2];
            #pragma unroll
            for (int v = 0; v < 2; v++) {
                float keep = (n & 2) ? q4[v + 2] : q4[v];
                float send = (n & 2) ? q4[v]     : q4[v + 2];
                q2[v] = keep + __shfl_xor_sync(0xffffffffu, send, 2);
            }
            float keep = (n & 1) ? q2[1] : q2[0];
            float send = (n & 1) ? q2[0] : q2[1];
            float ps = keep + __shfl_xor_sync(0xffffffffu, send, 1);

            float yv = fmaf(Dd, x_l, ps) * z_l;
            float yvp = __shfl_xor_sync(0xffffffffu, yv, 16);
            if (c2 == 0) {
                __nv_bfloat16 h0 = __float2bfloat16(yv);
                __nv_bfloat16 h1 = __float2bfloat16(yvp);
                __nv_bfloat16 l0 = __float2bfloat16(yv  - __bfloat162float(h0));
                __nv_bfloat16 l1 = __float2bfloat16(yvp - __bfloat162float(h1));
                size_t m = (size_t)(b * SEQ + t0 + n);
                *(__nv_bfloat162*)(g_yh + m * DINNER + d0) = __halves2bfloat162(h0, h1);
                *(__nv_bfloat162*)(g_yl + m * DINNER + d0) = __halves2bfloat162(l0, l1);
            }
        }
    }
}

// ---------------- launch ----------------
extern "C" void kernel_launch(void* const* d_in, const int* in_sizes, int n_in,
                              void* d_out, int out_size)
{
    const float* x          = (const float*)d_in[0];
    const float* in_proj_w  = (const float*)d_in[1];
    const float* conv_w     = (const float*)d_in[2];
    const float* conv_b     = (const float*)d_in[3];
    const float* A_log      = (const float*)d_in[4];
    const float* Dp         = (const float*)d_in[5];
    const float* x_proj_w   = (const float*)d_in[6];
    const float* dt_proj_w  = (const float*)d_in[7];
    const float* dt_proj_b  = (const float*)d_in[8];
    const float* out_proj_w = (const float*)d_in[9];
    float*       out        = (float*)d_out;

    float *xz, *xc, *xdblp, *dt;
    __nv_bfloat16 *xh, *xl, *wih, *wil, *yh, *yl, *woh, *wol, *dwh, *dwl, *x64h, *x64l;
    cudaGetSymbolAddress((void**)&xz,    g_xz);
    cudaGetSymbolAddress((void**)&xc,    g_xc);
    cudaGetSymbolAddress((void**)&xdblp, g_xdblp);
    cudaGetSymbolAddress((void**)&dt,    g_dt);
    cudaGetSymbolAddress((void**)&xh,   g_xh);
    cudaGetSymbolAddress((void**)&xl,   g_xl);
    cudaGetSymbolAddress((void**)&wih,  g_wih);
    cudaGetSymbolAddress((void**)&wil,  g_wil);
    cudaGetSymbolAddress((void**)&yh,   g_yh);
    cudaGetSymbolAddress((void**)&yl,   g_yl);
    cudaGetSymbolAddress((void**)&woh,  g_woh);
    cudaGetSymbolAddress((void**)&wol,  g_wol);
    cudaGetSymbolAddress((void**)&dwh,  g_dwh);
    cudaGetSymbolAddress((void**)&dwl,  g_dwl);
    cudaGetSymbolAddress((void**)&x64h, g_x64h);
    cudaGetSymbolAddress((void**)&x64l, g_x64l);

    cudaFuncSetAttribute(hmma_gemm<0>, cudaFuncAttributeMaxDynamicSharedMemorySize,
                         HMMA_SMEM);
    cudaFuncSetAttribute(hmma_gemm<1>, cudaFuncAttributeMaxDynamicSharedMemorySize,
                         HMMA_SMEM);

    // 0) bf16 hi/lo splits
    split_kernel<<<(MROWS*DMODEL + 255)/256, 256>>>(x, xh, xl, MROWS*DMODEL);
    split_kernel<<<(2*DINNER*DMODEL + 255)/256, 256>>>(in_proj_w, wih, wil, 2*DINNER*DMODEL);
    split_kernel<<<(DMODEL*DINNER + 255)/256, 256>>>(out_proj_w, woh, wol, DMODEL*DINNER);
    split_kernel<<<(DINNER*DTRANK + 255)/256, 256>>>(dt_proj_w, dwh, dwl, DINNER*DTRANK);

    // 1) xz = x @ in_proj_w^T  [4096,4096] K=1024
    hmma_gemm<0><<<dim3(32, 32), 256, HMMA_SMEM>>>(xh, xl, wih, wil, xz, nullptr,
                                                   DMODEL, 2*DINNER);

    // 2) causal depthwise conv + silu
    conv_silu_kernel<<<(MROWS * DINNER) / 256, 256>>>(conv_w, conv_b);

    // 3) x_dbl = xc @ x_proj_w^T — split-K x4 + routed reduce (B,C transposed)
    sgemm_splitk<<<dim3(1, 32, KSPLIT), 256>>>(xc, x_proj_w, xdblp,
                                               MROWS, XDBL_W, DINNER/KSPLIT,
                                               DINNER, DINNER);
    reduce_splitk_T<<<(MROWS*XDBL_W + 255)/256, 256>>>(xdblp);

    // 3b) split xdbl[:, :64] to packed bf16 hi/lo
    split_x64_kernel<<<(MROWS*DTRANK + 255)/256, 256>>>();

    // 4) dt = softplus(xdbl64 @ dt_proj_w^T + b)  [4096,2048] K=64 — HMMA
    hmma_gemm<1><<<dim3(16, 32), 256, HMMA_SMEM>>>(x64h, x64l, dwh, dwl, dt, dt_proj_b,
                                                   DTRANK, DINNER);

    // 4b) transposes: dt->dtT, xc->xcT, silu(z)->zsT
    transpose3_kernel<<<dim3(64, 128, 3), 256>>>();

    // 5) selective scan v5
    scan_kernel<<<256, 256>>>(A_log, Dp);

    // 6) out = y @ out_proj_w^T  [4096,1024] K=2048
    hmma_gemm<0><<<dim3(8, 32), 256, HMMA_SMEM>>>(yh, yl, woh, wol, out, nullptr,
                                                  DINNER, DMODEL);
}

// round 16
// speedup vs baseline: 1.5152x; 1.0009x over previous
#include <cuda_runtime.h>
#include <cuda_bf16.h>
#include <math.h>
#include <stdint.h>

#define B_SZ   2
#define SEQ    2048
#define DMODEL 1024
#define DINNER 2048
#define DSTATE 16
#define DTRANK 64
#define DCONV  4
#define MROWS  (B_SZ*SEQ)   // 4096
#define XDBL_W 96
#define KSPLIT 8

// ---------------- scratch ----------------
__device__ float g_xz   [(size_t)MROWS * 2 * DINNER];
__device__ float g_xc   [(size_t)MROWS * DINNER];
__device__ float g_xdbl [(size_t)MROWS * XDBL_W];
__device__ float g_xdblp[(size_t)KSPLIT * MROWS * XDBL_W];
__device__ float g_dt   [(size_t)MROWS * DINNER];

// channel-major transposed arrays for the scan
__device__ float g_dtT  [(size_t)MROWS * DINNER];
__device__ float g_xcT  [(size_t)MROWS * DINNER];
__device__ float g_zsT  [(size_t)MROWS * DINNER];
__device__ float g_BT   [(size_t)B_SZ * DSTATE * SEQ];
__device__ float g_CT   [(size_t)B_SZ * DSTATE * SEQ];

// bf16 hi/lo splits
__device__ __nv_bfloat16 g_xh  [(size_t)MROWS * DMODEL];
__device__ __nv_bfloat16 g_xl  [(size_t)MROWS * DMODEL];
__device__ __nv_bfloat16 g_wih [(size_t)(2*DINNER) * DMODEL];
__device__ __nv_bfloat16 g_wil [(size_t)(2*DINNER) * DMODEL];
__device__ __nv_bfloat16 g_yh  [(size_t)MROWS * DINNER];
__device__ __nv_bfloat16 g_yl  [(size_t)MROWS * DINNER];
__device__ __nv_bfloat16 g_woh [(size_t)DMODEL * DINNER];
__device__ __nv_bfloat16 g_wol [(size_t)DMODEL * DINNER];
__device__ __nv_bfloat16 g_x64h[(size_t)MROWS * DTRANK];
__device__ __nv_bfloat16 g_x64l[(size_t)MROWS * DTRANK];
__device__ __nv_bfloat16 g_dwh [(size_t)DINNER * DTRANK];
__device__ __nv_bfloat16 g_dwl [(size_t)DINNER * DTRANK];

// ======================= helpers =======================
__device__ __forceinline__ uint32_t smem_to_u32(const void* p) {
    uint32_t a;
    asm("{ .reg .u64 t; cvta.to.shared.u64 t, %1; cvt.u32.u64 %0, t; }"
        : "=r"(a) : "l"(p));
    return a;
}

#define LDM_X4(r, addr) \
    asm volatile("ldmatrix.sync.aligned.m8n8.x4.shared.b16 {%0,%1,%2,%3}, [%4];" \
        : "=r"((r)[0]), "=r"((r)[1]), "=r"((r)[2]), "=r"((r)[3]) : "r"(addr))

#define MMA16816(c, a, b0, b1) \
    asm volatile("mma.sync.aligned.m16n8k16.row.col.f32.bf16.bf16.f32 " \
        "{%0,%1,%2,%3}, {%4,%5,%6,%7}, {%8,%9}, {%0,%1,%2,%3};" \
        : "+f"((c)[0]), "+f"((c)[1]), "+f"((c)[2]), "+f"((c)[3]) \
        : "r"((a)[0]), "r"((a)[1]), "r"((a)[2]), "r"((a)[3]), "r"(b0), "r"(b1))

#define CP_ASYNC16(saddr, gptr) \
    asm volatile("cp.async.cg.shared.global [%0], [%1], 16;" \
        :: "r"(saddr), "l"(gptr) : "memory")
#define CP_COMMIT() asm volatile("cp.async.commit_group;" ::: "memory")
#define CP_WAIT(n)  asm volatile("cp.async.wait_group %0;" :: "n"(n) : "memory")

// ====== split-bf16 HMMA GEMM (R7 config): 128x128 tile, 256 thr, 64x32 warps ==
// EPI: 0 = none, 1 = softplus(v + bias[col])
#define LDSH   40
#define STG_H  (128*LDSH)
#define STAGE_H (4*STG_H)
#define HMMA_SMEM (2*STAGE_H*2)      // 81920 bytes -> 2 CTAs/SM

template<int EPI>
__global__ void __launch_bounds__(256, 1)
hmma_gemm(const __nv_bfloat16* __restrict__ Ah, const __nv_bfloat16* __restrict__ Al,
          const __nv_bfloat16* __restrict__ Bh, const __nv_bfloat16* __restrict__ Bl,
          float* __restrict__ C, const float* __restrict__ bias, int K, int N)
{
    extern __shared__ __nv_bfloat16 sm[];
    const int tid  = threadIdx.x;
    const int lane = tid & 31;
    const int w    = tid >> 5;
    const int wm   = w >> 2;          // 0..1
    const int wn   = w & 3;           // 0..3
    const int row0 = blockIdx.y * 128;
    const int col0 = blockIdx.x * 128;
    const uint32_t sbase = smem_to_u32(sm);

    const int nc = K >> 5;

    auto load_stage = [&](int c, int s) {
        #pragma unroll
        for (int j = 0; j < 2; j++) {
            int i = tid + j * 256;
            int r = i >> 2, q = i & 3;
            size_t gA = (size_t)(row0 + r) * K + c * 32 + q * 8;
            size_t gB = (size_t)(col0 + r) * K + c * 32 + q * 8;
            uint32_t sa = sbase + (uint32_t)(s * STAGE_H + r * LDSH + q * 8) * 2;
            CP_ASYNC16(sa,                (const void*)(Ah + gA));
            CP_ASYNC16(sa + STG_H*2,      (const void*)(Al + gA));
            CP_ASYNC16(sa + 2*STG_H*2,    (const void*)(Bh + gB));
            CP_ASYNC16(sa + 3*STG_H*2,    (const void*)(Bl + gB));
        }
    };

    float acc[4][4][4];
    #pragma unroll
    for (int mi = 0; mi < 4; mi++)
        #pragma unroll
        for (int nj = 0; nj < 4; nj++)
            #pragma unroll
            for (int q = 0; q < 4; q++) acc[mi][nj][q] = 0.f;

    load_stage(0, 0);
    CP_COMMIT();

    for (int c = 0; c < nc; c++) {
        int s = c & 1;
        if (c + 1 < nc) {
            load_stage(c + 1, (c + 1) & 1);
            CP_COMMIT();
            CP_WAIT(1);
        } else {
            CP_WAIT(0);
        }
        __syncthreads();

        #pragma unroll
        for (int ks = 0; ks < 2; ks++) {
            uint32_t ah[4][4], al[4][4];
            #pragma unroll
            for (int mi = 0; mi < 4; mi++) {
                uint32_t off = (uint32_t)(s * STAGE_H
                             + (wm*64 + mi*16 + (lane & 15)) * LDSH
                             + ks*16 + (lane >> 4) * 8);
                uint32_t ad = sbase + off * 2;
                LDM_X4(ah[mi], ad);
                LDM_X4(al[mi], ad + STG_H*2);
            }
            uint32_t bh[2][4], bl[2][4];
            #pragma unroll
            for (int np = 0; np < 2; np++) {
                uint32_t off = (uint32_t)(s * STAGE_H + 2*STG_H
                             + (wn*32 + np*16 + (lane & 7) + ((lane >> 3) & 1) * 8) * LDSH
                             + ks*16 + (lane >> 4) * 8);
                uint32_t bd = sbase + off * 2;
                LDM_X4(bh[np], bd);
                LDM_X4(bl[np], bd + STG_H*2);
            }
            #pragma unroll
            for (int mi = 0; mi < 4; mi++)
                #pragma unroll
                for (int np = 0; np < 2; np++)
                    #pragma unroll
                    for (int sub = 0; sub < 2; sub++) {
                        int nj = np * 2 + sub;
                        MMA16816(acc[mi][nj], ah[mi], bh[np][sub], bh[np][sub + 2]);
                        MMA16816(acc[mi][nj], ah[mi], bl[np][sub], bl[np][sub + 2]);
                        MMA16816(acc[mi][nj], al[mi], bh[np][sub], bh[np][sub + 2]);
                    }
        }
        __syncthreads();
    }

    #pragma unroll
    for (int mi = 0; mi < 4; mi++)
        #pragma unroll
        for (int nj = 0; nj < 4; nj++) {
            int r  = row0 + wm*64 + mi*16 + (lane >> 2);
            int cc = col0 + wn*32 + nj*8 + (lane & 3) * 2;
            float v0 = acc[mi][nj][0], v1 = acc[mi][nj][1];
            float v2 = acc[mi][nj][2], v3 = acc[mi][nj][3];
            if (EPI == 1) {
                float b0 = bias[cc], b1 = bias[cc + 1];
                v0 += b0; v1 += b1; v2 += b0; v3 += b1;
                v0 = (v0 > 20.f) ? v0 : log1pf(__expf(v0));
                v1 = (v1 > 20.f) ? v1 : log1pf(__expf(v1));
                v2 = (v2 > 20.f) ? v2 : log1pf(__expf(v2));
                v3 = (v3 > 20.f) ? v3 : log1pf(__expf(v3));
            }
            *(float2*)(C + (size_t)r * N + cc)       = make_float2(v0, v1);
            *(float2*)(C + (size_t)(r + 8) * N + cc) = make_float2(v2, v3);
        }
}

// ---------------- fp32 -> bf16 hi/lo split ----------------
__global__ void split_kernel(const float* __restrict__ src,
                             __nv_bfloat16* __restrict__ hi,
                             __nv_bfloat16* __restrict__ lo, int n)
{
    int i = blockIdx.x * blockDim.x + threadIdx.x;
    if (i < n) {
        float v = src[i];
        __nv_bfloat16 h = __float2bfloat16(v);
        hi[i] = h;
        lo[i] = __float2bfloat16(v - __bfloat162float(h));
    }
}

// strided split: xdbl[:, 0:64] -> packed [MROWS,64] hi/lo
__global__ void split_x64_kernel()
{
    int i = blockIdx.x * blockDim.x + threadIdx.x;
    if (i < MROWS * DTRANK) {
        int row = i >> 6, col = i & 63;
        float v = g_xdbl[row * XDBL_W + col];
        __nv_bfloat16 h = __float2bfloat16(v);
        g_x64h[i] = h;
        g_x64l[i] = __float2bfloat16(v - __bfloat162float(h));
    }
}

// ---------------- split-K SIMT GEMM for x_proj ------
__global__ void __launch_bounds__(256, 2) sgemm_splitk(
    const float* __restrict__ A, const float* __restrict__ Bw,
    float* __restrict__ Cpart, int M, int N, int Kc, int lda, int ldb)
{
    __shared__ float As[8][128];
    __shared__ float Bs[8][128];
    int tid  = threadIdx.x;
    int row0 = blockIdx.y * 128;
    int col0 = blockIdx.x * 128;
    int z    = blockIdx.z;
    int tx = tid & 15, ty = tid >> 4;
    int ldRow = tid >> 1, ldCol = (tid & 1) * 4;

    float acc[8][8];
    #pragma unroll
    for (int i = 0; i < 8; i++)
        #pragma unroll
        for (int j = 0; j < 8; j++) acc[i][j] = 0.f;

    const float* Aptr = A + (size_t)(row0 + ldRow) * lda + z * Kc + ldCol;
    bool bValid = (col0 + ldRow) < N;
    const float* Bptr = Bw + (size_t)(col0 + ldRow) * ldb + z * Kc + ldCol;

    for (int k0 = 0; k0 < Kc; k0 += 8) {
        float4 av = *(const float4*)(Aptr + k0);
        float4 bv = bValid ? *(const float4*)(Bptr + k0) : make_float4(0.f,0.f,0.f,0.f);
        As[ldCol+0][ldRow] = av.x; As[ldCol+1][ldRow] = av.y;
        As[ldCol+2][ldRow] = av.z; As[ldCol+3][ldRow] = av.w;
        Bs[ldCol+0][ldRow] = bv.x; Bs[ldCol+1][ldRow] = bv.y;
        Bs[ldCol+2][ldRow] = bv.z; Bs[ldCol+3][ldRow] = bv.w;
        __syncthreads();
        #pragma unroll
        for (int kk = 0; kk < 8; kk++) {
            float a[8], b[8];
            *(float4*)(a)     = *(const float4*)&As[kk][ty*8];
            *(float4*)(a + 4) = *(const float4*)&As[kk][ty*8+4];
            *(float4*)(b)     = *(const float4*)&Bs[kk][tx*8];
            *(float4*)(b + 4) = *(const float4*)&Bs[kk][tx*8+4];
            #pragma unroll
            for (int i = 0; i < 8; i++)
                #pragma unroll
                for (int j = 0; j < 8; j++)
                    acc[i][j] = fmaf(a[i], b[j], acc[i][j]);
        }
        __syncthreads();
    }
    float* Cz = Cpart + (size_t)z * M * N;
    #pragma unroll
    for (int i = 0; i < 8; i++) {
        int r = row0 + ty*8 + i;
        #pragma unroll
        for (int j = 0; j < 8; j++) {
            int c = col0 + tx*8 + j;
            if (c < N) Cz[(size_t)r * N + c] = acc[i][j];
        }
    }
}

// reduce split-K partials; route dt cols to xdbl, B/C cols to transposed arrays
__global__ void reduce_splitk_T(const float* __restrict__ parts)
{
    const int total = MROWS * XDBL_W;
    int i = blockIdx.x * blockDim.x + threadIdx.x;
    if (i >= total) return;
    float v = 0.f;
    #pragma unroll
    for (int z = 0; z < KSPLIT; z++) v += parts[i + (size_t)z * total];
    int m = i / XDBL_W;
    int c = i - m * XDBL_W;
    if (c < DTRANK) {
        g_xdbl[i] = v;
    } else {
        int b = m >> 11, t = m & (SEQ - 1);
        int cc = c - DTRANK;          // 0..31
        if (cc < DSTATE) g_BT[(size_t)(b*DSTATE + cc) * SEQ + t] = v;
        else             g_CT[(size_t)(b*DSTATE + cc - DSTATE) * SEQ + t] = v;
    }
}

// ---------------- causal depthwise conv (k=4) + SiLU ----------------
__global__ void conv_silu_kernel(const float* __restrict__ conv_w,
                                 const float* __restrict__ conv_b)
{
    int idx = blockIdx.x * blockDim.x + threadIdx.x;
    int d = idx & (DINNER - 1);
    int m = idx >> 11;
    int l = m & (SEQ - 1);
    int b = m >> 11;
    float s = conv_b[d];
    #pragma unroll
    for (int j = 0; j < DCONV; j++) {
        int li = l - (DCONV - 1) + j;
        if (li >= 0)
            s = fmaf(conv_w[d * DCONV + j],
                     g_xz[(size_t)(b * SEQ + li) * (2 * DINNER) + d], s);
    }
    g_xc[idx] = s / (1.f + __expf(-s));
}

// ---------------- batched tiled transpose: dt->dtT, xc->xcT, silu(z)->zsT ----
__global__ void __launch_bounds__(256) transpose3_kernel()
{
    __shared__ float tile[32][33];
    int zsel = blockIdx.z;
    int b  = blockIdx.y >> 6;
    int t0 = (blockIdx.y & 63) << 5;
    int d0 = blockIdx.x << 5;
    int tx = threadIdx.x & 31, ty = threadIdx.x >> 5;

    const float* src; int stride;
    if (zsel == 0)      { src = g_dt;          stride = DINNER;   }
    else if (zsel == 1) { src = g_xc;          stride = DINNER;   }
    else                { src = g_xz + DINNER; stride = 2*DINNER; }

    #pragma unroll
    for (int k = 0; k < 32; k += 8) {
        float v = src[(size_t)(b*SEQ + t0 + ty + k) * stride + d0 + tx];
        if (zsel == 2) v = v / (1.f + __expf(-v));
        tile[ty + k][tx] = v;
    }
    __syncthreads();
    float* dst = (zsel == 0) ? g_dtT : (zsel == 1) ? g_xcT : g_zsT;
    #pragma unroll
    for (int k = 0; k < 32; k += 8)
        dst[(size_t)(b*DINNER + d0 + ty + k) * SEQ + t0 + tx] = tile[tx][ty + k];
}

// ---------------- selective scan v5: smem B/C tiles, packed stores ----------
#define UNR2 16
#define T_TILE 128
#define SPAD 132
__global__ void __launch_bounds__(256) scan_kernel(const float* __restrict__ A_log,
                                                   const float* __restrict__ Dp)
{
    __shared__ float sB[DSTATE][SPAD];
    __shared__ float sC[DSTATE][SPAD];

    int tid  = threadIdx.x;
    int lane = tid & 31;
    int warp = tid >> 5;
    int c2 = lane >> 4;
    int n  = lane & 15;
    int ch = blockIdx.x * 16 + warp * 2 + c2;
    int b  = ch >> 11;
    int d  = ch & (DINNER - 1);
    int d0 = d & ~1;

    float Ac = -__expf(__ldg(A_log + d * DSTATE + n));
    float Dd = Dp[d];
    float h  = 0.f;

    const float* dtT = g_dtT + (size_t)ch * SEQ;
    const float* xT  = g_xcT + (size_t)ch * SEQ;
    const float* zT  = g_zsT + (size_t)ch * SEQ;
    const float* BTb = g_BT  + (size_t)b * DSTATE * SEQ;
    const float* CTb = g_CT  + (size_t)b * DSTATE * SEQ;
    int srcbase = c2 << 4;

    int ldr = tid >> 5;
    int ldc = (tid & 31) * 4;

    for (int tb = 0; tb < SEQ; tb += T_TILE) {
        __syncthreads();
        #pragma unroll
        for (int rr = 0; rr < 2; rr++) {
            int r = ldr + rr * 8;
            float4 bv = *(const float4*)(BTb + (size_t)r * SEQ + tb + ldc);
            float4 cv = *(const float4*)(CTb + (size_t)r * SEQ + tb + ldc);
            *(float4*)&sB[r][ldc] = bv;
            *(float4*)&sC[r][ldc] = cv;
        }
        __syncthreads();

        for (int tt = 0; tt < T_TILE; tt += UNR2) {
            int t0 = tb + tt;
            float dt_l = __ldg(dtT + t0 + n);
            float x_l  = __ldg(xT  + t0 + n);
            float z_l  = __ldg(zT  + t0 + n);
            float pre_l = dt_l * x_l;

            float Bn[UNR2], Cn[UNR2];
            #pragma unroll
            for (int q = 0; q < UNR2; q += 4) {
                float4 bq = *(const float4*)&sB[n][tt + q];
                float4 cq = *(const float4*)&sC[n][tt + q];
                Bn[q] = bq.x; Bn[q+1] = bq.y; Bn[q+2] = bq.z; Bn[q+3] = bq.w;
                Cn[q] = cq.x; Cn[q+1] = cq.y; Cn[q+2] = cq.z; Cn[q+3] = cq.w;
            }

            float dA[UNR2];
            #pragma unroll
            for (int u = 0; u < UNR2; u++) {
                float dtu  = __shfl_sync(0xffffffffu, dt_l,  srcbase + u);
                float preu = __shfl_sync(0xffffffffu, pre_l, srcbase + u);
                Bn[u] = preu * Bn[u];
                dA[u] = __expf(dtu * Ac);
            }

            float p[UNR2];
            #pragma unroll
            for (int u = 0; u < UNR2; u++) {
                h = fmaf(dA[u], h, Bn[u]);
                p[u] = h * Cn[u];
            }

            // reduce-scatter: lane n ends with sum for timestep t0+n
            float q8[8];
            #pragma unroll
            for (int v = 0; v < 8; v++) {
                float keep = (n & 8) ? p[v + 8] : p[v];
                float send = (n & 8) ? p[v]     : p[v + 8];
                q8[v] = keep + __shfl_xor_sync(0xffffffffu, send, 8);
            }
            float q4[4];
            #pragma unroll
            for (int v = 0; v < 4; v++) {
                float keep = (n & 4) ? q8[v + 4] : q8[v];
                float send = (n & 4) ? q8[v]     : q8[v + 4];
                q4[v] = keep + __shfl_xor_sync(0xffffffffu, send, 4);
            }
            float q2[2];
            #pragma unroll
            for (int v = 0; v < 2; v++) {
                float keep = (n & 2) ? q4[v + 2] : q4[v];
                float send = (n & 2) ? q4[v]     : q4[v + 2];
                q2[v] = keep + __shfl_xor_sync(0xffffffffu, send, 2);
            }
            float keep = (n & 1) ? q2[1] : q2[0];
            float send = (n & 1) ? q2[0] : q2[1];
            float ps = keep + __shfl_xor_sync(0xffffffffu, send, 1);

            float yv = fmaf(Dd, x_l, ps) * z_l;
            float yvp = __shfl_xor_sync(0xffffffffu, yv, 16);
            if (c2 == 0) {
                __nv_bfloat16 h0 = __float2bfloat16(yv);
                __nv_bfloat16 h1 = __float2bfloat16(yvp);
                __nv_bfloat16 l0 = __float2bfloat16(yv  - __bfloat162float(h0));
                __nv_bfloat16 l1 = __float2bfloat16(yvp - __bfloat162float(h1));
                size_t m = (size_t)(b * SEQ + t0 + n);
                *(__nv_bfloat162*)(g_yh + m * DINNER + d0) = __halves2bfloat162(h0, h1);
                *(__nv_bfloat162*)(g_yl + m * DINNER + d0) = __halves2bfloat162(l0, l1);
            }
        }
    }
}

// ---------------- launch ----------------
extern "C" void kernel_launch(void* const* d_in, const int* in_sizes, int n_in,
                              void* d_out, int out_size)
{
    const float* x          = (const float*)d_in[0];
    const float* in_proj_w  = (const float*)d_in[1];
    const float* conv_w     = (const float*)d_in[2];
    const float* conv_b     = (const float*)d_in[3];
    const float* A_log      = (const float*)d_in[4];
    const float* Dp         = (const float*)d_in[5];
    const float* x_proj_w   = (const float*)d_in[6];
    const float* dt_proj_w  = (const float*)d_in[7];
    const float* dt_proj_b  = (const float*)d_in[8];
    const float* out_proj_w = (const float*)d_in[9];
    float*       out        = (float*)d_out;

    float *xz, *xc, *xdblp, *dt;
    __nv_bfloat16 *xh, *xl, *wih, *wil, *yh, *yl, *woh, *wol, *dwh, *dwl, *x64h, *x64l;
    cudaGetSymbolAddress((void**)&xz,    g_xz);
    cudaGetSymbolAddress((void**)&xc,    g_xc);
    cudaGetSymbolAddress((void**)&xdblp, g_xdblp);
    cudaGetSymbolAddress((void**)&dt,    g_dt);
    cudaGetSymbolAddress((void**)&xh,   g_xh);
    cudaGetSymbolAddress((void**)&xl,   g_xl);
    cudaGetSymbolAddress((void**)&wih,  g_wih);
    cudaGetSymbolAddress((void**)&wil,  g_wil);
    cudaGetSymbolAddress((void**)&yh,   g_yh);
    cudaGetSymbolAddress((void**)&yl,   g_yl);
    cudaGetSymbolAddress((void**)&woh,  g_woh);
    cudaGetSymbolAddress((void**)&wol,  g_wol);
    cudaGetSymbolAddress((void**)&dwh,  g_dwh);
    cudaGetSymbolAddress((void**)&dwl,  g_dwl);
    cudaGetSymbolAddress((void**)&x64h, g_x64h);
    cudaGetSymbolAddress((void**)&x64l, g_x64l);

    cudaFuncSetAttribute(hmma_gemm<0>, cudaFuncAttributeMaxDynamicSharedMemorySize,
                         HMMA_SMEM);
    cudaFuncSetAttribute(hmma_gemm<1>, cudaFuncAttributeMaxDynamicSharedMemorySize,
                         HMMA_SMEM);

    // 0) bf16 hi/lo splits
    split_kernel<<<(MROWS*DMODEL + 255)/256, 256>>>(x, xh, xl, MROWS*DMODEL);
    split_kernel<<<(2*DINNER*DMODEL + 255)/256, 256>>>(in_proj_w, wih, wil, 2*DINNER*DMODEL);
    split_kernel<<<(DMODEL*DINNER + 255)/256, 256>>>(out_proj_w, woh, wol, DMODEL*DINNER);
    split_kernel<<<(DINNER*DTRANK + 255)/256, 256>>>(dt_proj_w, dwh, dwl, DINNER*DTRANK);

    // 1) xz = x @ in_proj_w^T  [4096,4096] K=1024
    hmma_gemm<0><<<dim3(32, 32), 256, HMMA_SMEM>>>(xh, xl, wih, wil, xz, nullptr,
                                                   DMODEL, 2*DINNER);

    // 2) causal depthwise conv + silu
    conv_silu_kernel<<<(MROWS * DINNER) / 256, 256>>>(conv_w, conv_b);

    // 3) x_dbl = xc @ x_proj_w^T — split-K x8 + routed reduce (B,C transposed)
    sgemm_splitk<<<dim3(1, 32, KSPLIT), 256>>>(xc, x_proj_w, xdblp,
                                               MROWS, XDBL_W, DINNER/KSPLIT,
                                               DINNER, DINNER);
    reduce_splitk_T<<<(MROWS*XDBL_W + 255)/256, 256>>>(xdblp);

    // 3b) split xdbl[:, :64] to packed bf16 hi/lo
    split_x64_kernel<<<(MROWS*DTRANK + 255)/256, 256>>>();

    // 4) dt = softplus(xdbl64 @ dt_proj_w^T + b)  [4096,2048] K=64 — HMMA
    hmma_gemm<1><<<dim3(16, 32), 256, HMMA_SMEM>>>(x64h, x64l, dwh, dwl, dt, dt_proj_b,
                                                   DTRANK, DINNER);

    // 4b) transposes: dt->dtT, xc->xcT, silu(z)->zsT
    transpose3_kernel<<<dim3(64, 128, 3), 256>>>();

    // 5) selective scan v5
    scan_kernel<<<256, 256>>>(A_log, Dp);

    // 6) out = y @ out_proj_w^T  [4096,1024] K=2048
    hmma_gemm<0><<<dim3(8, 32), 256, HMMA_SMEM>>>(yh, yl, woh, wol, out, nullptr,
                                                  DINNER, DMODEL);
}

// round 17
// speedup vs baseline: 1.5628x; 1.0314x over previous
#include <cuda_runtime.h>
#include <cuda_bf16.h>
#include <math.h>
#include <stdint.h>

#define B_SZ   2
#define SEQ    2048
#define DMODEL 1024
#define DINNER 2048
#define DSTATE 16
#define DTRANK 64
#define DCONV  4
#define MROWS  (B_SZ*SEQ)   // 4096
#define XDBL_W 96
#define KSPLIT 8

// ---------------- scratch ----------------
__device__ float g_xz   [(size_t)MROWS * 2 * DINNER];
__device__ float g_xc   [(size_t)MROWS * DINNER];
__device__ float g_xdbl [(size_t)MROWS * XDBL_W];
__device__ float g_xdblp[(size_t)KSPLIT * MROWS * XDBL_W];
__device__ float g_dt   [(size_t)MROWS * DINNER];

// channel-major transposed arrays for the scan
__device__ float g_dtT  [(size_t)MROWS * DINNER];
__device__ float g_xcT  [(size_t)MROWS * DINNER];
__device__ float g_zsT  [(size_t)MROWS * DINNER];
__device__ float g_BT   [(size_t)B_SZ * DSTATE * SEQ];
__device__ float g_CT   [(size_t)B_SZ * DSTATE * SEQ];

// bf16 hi/lo splits
__device__ __nv_bfloat16 g_xh  [(size_t)MROWS * DMODEL];
__device__ __nv_bfloat16 g_xl  [(size_t)MROWS * DMODEL];
__device__ __nv_bfloat16 g_wih [(size_t)(2*DINNER) * DMODEL];
__device__ __nv_bfloat16 g_wil [(size_t)(2*DINNER) * DMODEL];
__device__ __nv_bfloat16 g_yh  [(size_t)MROWS * DINNER];
__device__ __nv_bfloat16 g_yl  [(size_t)MROWS * DINNER];
__device__ __nv_bfloat16 g_woh [(size_t)DMODEL * DINNER];
__device__ __nv_bfloat16 g_wol [(size_t)DMODEL * DINNER];
__device__ __nv_bfloat16 g_x64h[(size_t)MROWS * DTRANK];
__device__ __nv_bfloat16 g_x64l[(size_t)MROWS * DTRANK];
__device__ __nv_bfloat16 g_dwh [(size_t)DINNER * DTRANK];
__device__ __nv_bfloat16 g_dwl [(size_t)DINNER * DTRANK];

// ======================= helpers =======================
__device__ __forceinline__ uint32_t smem_to_u32(const void* p) {
    uint32_t a;
    asm("{ .reg .u64 t; cvta.to.shared.u64 t, %1; cvt.u32.u64 %0, t; }"
        : "=r"(a) : "l"(p));
    return a;
}

#define LDM_X4(r, addr) \
    asm volatile("ldmatrix.sync.aligned.m8n8.x4.shared.b16 {%0,%1,%2,%3}, [%4];" \
        : "=r"((r)[0]), "=r"((r)[1]), "=r"((r)[2]), "=r"((r)[3]) : "r"(addr))

#define MMA16816(c, a, b0, b1) \
    asm volatile("mma.sync.aligned.m16n8k16.row.col.f32.bf16.bf16.f32 " \
        "{%0,%1,%2,%3}, {%4,%5,%6,%7}, {%8,%9}, {%0,%1,%2,%3};" \
        : "+f"((c)[0]), "+f"((c)[1]), "+f"((c)[2]), "+f"((c)[3]) \
        : "r"((a)[0]), "r"((a)[1]), "r"((a)[2]), "r"((a)[3]), "r"(b0), "r"(b1))

#define CP_ASYNC16(saddr, gptr) \
    asm volatile("cp.async.cg.shared.global [%0], [%1], 16;" \
        :: "r"(saddr), "l"(gptr) : "memory")
#define CP_COMMIT() asm volatile("cp.async.commit_group;" ::: "memory")
#define CP_WAIT(n)  asm volatile("cp.async.wait_group %0;" :: "n"(n) : "memory")

// ====== split-bf16 HMMA GEMM (R7 config): 128x128 tile, 256 thr, 64x32 warps ==
#define LDSH   40
#define STG_H  (128*LDSH)
#define STAGE_H (4*STG_H)
#define HMMA_SMEM (2*STAGE_H*2)      // 81920 bytes -> 2 CTAs/SM

template<int EPI>
__global__ void __launch_bounds__(256, 1)
hmma_gemm(const __nv_bfloat16* __restrict__ Ah, const __nv_bfloat16* __restrict__ Al,
          const __nv_bfloat16* __restrict__ Bh, const __nv_bfloat16* __restrict__ Bl,
          float* __restrict__ C, const float* __restrict__ bias, int K, int N)
{
    extern __shared__ __nv_bfloat16 sm[];
    const int tid  = threadIdx.x;
    const int lane = tid & 31;
    const int w    = tid >> 5;
    const int wm   = w >> 2;
    const int wn   = w & 3;
    const int row0 = blockIdx.y * 128;
    const int col0 = blockIdx.x * 128;
    const uint32_t sbase = smem_to_u32(sm);

    const int nc = K >> 5;

    auto load_stage = [&](int c, int s) {
        #pragma unroll
        for (int j = 0; j < 2; j++) {
            int i = tid + j * 256;
            int r = i >> 2, q = i & 3;
            size_t gA = (size_t)(row0 + r) * K + c * 32 + q * 8;
            size_t gB = (size_t)(col0 + r) * K + c * 32 + q * 8;
            uint32_t sa = sbase + (uint32_t)(s * STAGE_H + r * LDSH + q * 8) * 2;
            CP_ASYNC16(sa,                (const void*)(Ah + gA));
            CP_ASYNC16(sa + STG_H*2,      (const void*)(Al + gA));
            CP_ASYNC16(sa + 2*STG_H*2,    (const void*)(Bh + gB));
            CP_ASYNC16(sa + 3*STG_H*2,    (const void*)(Bl + gB));
        }
    };

    float acc[4][4][4];
    #pragma unroll
    for (int mi = 0; mi < 4; mi++)
        #pragma unroll
        for (int nj = 0; nj < 4; nj++)
            #pragma unroll
            for (int q = 0; q < 4; q++) acc[mi][nj][q] = 0.f;

    load_stage(0, 0);
    CP_COMMIT();

    for (int c = 0; c < nc; c++) {
        int s = c & 1;
        if (c + 1 < nc) {
            load_stage(c + 1, (c + 1) & 1);
            CP_COMMIT();
            CP_WAIT(1);
        } else {
            CP_WAIT(0);
        }
        __syncthreads();

        #pragma unroll
        for (int ks = 0; ks < 2; ks++) {
            uint32_t ah[4][4], al[4][4];
            #pragma unroll
            for (int mi = 0; mi < 4; mi++) {
                uint32_t off = (uint32_t)(s * STAGE_H
                             + (wm*64 + mi*16 + (lane & 15)) * LDSH
                             + ks*16 + (lane >> 4) * 8);
                uint32_t ad = sbase + off * 2;
                LDM_X4(ah[mi], ad);
                LDM_X4(al[mi], ad + STG_H*2);
            }
            uint32_t bh[2][4], bl[2][4];
            #pragma unroll
            for (int np = 0; np < 2; np++) {
                uint32_t off = (uint32_t)(s * STAGE_H + 2*STG_H
                             + (wn*32 + np*16 + (lane & 7) + ((lane >> 3) & 1) * 8) * LDSH
                             + ks*16 + (lane >> 4) * 8);
                uint32_t bd = sbase + off * 2;
                LDM_X4(bh[np], bd);
                LDM_X4(bl[np], bd + STG_H*2);
            }
            #pragma unroll
            for (int mi = 0; mi < 4; mi++)
                #pragma unroll
                for (int np = 0; np < 2; np++)
                    #pragma unroll
                    for (int sub = 0; sub < 2; sub++) {
                        int nj = np * 2 + sub;
                        MMA16816(acc[mi][nj], ah[mi], bh[np][sub], bh[np][sub + 2]);
                        MMA16816(acc[mi][nj], ah[mi], bl[np][sub], bl[np][sub + 2]);
                        MMA16816(acc[mi][nj], al[mi], bh[np][sub], bh[np][sub + 2]);
                    }
        }
        __syncthreads();
    }

    #pragma unroll
    for (int mi = 0; mi < 4; mi++)
        #pragma unroll
        for (int nj = 0; nj < 4; nj++) {
            int r  = row0 + wm*64 + mi*16 + (lane >> 2);
            int cc = col0 + wn*32 + nj*8 + (lane & 3) * 2;
            float v0 = acc[mi][nj][0], v1 = acc[mi][nj][1];
            float v2 = acc[mi][nj][2], v3 = acc[mi][nj][3];
            if (EPI == 1) {
                float b0 = bias[cc], b1 = bias[cc + 1];
                v0 += b0; v1 += b1; v2 += b0; v3 += b1;
                v0 = (v0 > 20.f) ? v0 : log1pf(__expf(v0));
                v1 = (v1 > 20.f) ? v1 : log1pf(__expf(v1));
                v2 = (v2 > 20.f) ? v2 : log1pf(__expf(v2));
                v3 = (v3 > 20.f) ? v3 : log1pf(__expf(v3));
            }
            *(float2*)(C + (size_t)r * N + cc)       = make_float2(v0, v1);
            *(float2*)(C + (size_t)(r + 8) * N + cc) = make_float2(v2, v3);
        }
}

// ---------------- fp32 -> bf16 hi/lo split ----------------
__global__ void split_kernel(const float* __restrict__ src,
                             __nv_bfloat16* __restrict__ hi,
                             __nv_bfloat16* __restrict__ lo, int n)
{
    int i = blockIdx.x * blockDim.x + threadIdx.x;
    if (i < n) {
        float v = src[i];
        __nv_bfloat16 h = __float2bfloat16(v);
        hi[i] = h;
        lo[i] = __float2bfloat16(v - __bfloat162float(h));
    }
}

// strided split: xdbl[:, 0:64] -> packed [MROWS,64] hi/lo
__global__ void split_x64_kernel()
{
    int i = blockIdx.x * blockDim.x + threadIdx.x;
    if (i < MROWS * DTRANK) {
        int row = i >> 6, col = i & 63;
        float v = g_xdbl[row * XDBL_W + col];
        __nv_bfloat16 h = __float2bfloat16(v);
        g_x64h[i] = h;
        g_x64l[i] = __float2bfloat16(v - __bfloat162float(h));
    }
}

// ---------------- split-K SIMT GEMM for x_proj ------
__global__ void __launch_bounds__(256, 2) sgemm_splitk(
    const float* __restrict__ A, const float* __restrict__ Bw,
    float* __restrict__ Cpart, int M, int N, int Kc, int lda, int ldb)
{
    __shared__ float As[8][128];
    __shared__ float Bs[8][128];
    int tid  = threadIdx.x;
    int row0 = blockIdx.y * 128;
    int col0 = blockIdx.x * 128;
    int z    = blockIdx.z;
    int tx = tid & 15, ty = tid >> 4;
    int ldRow = tid >> 1, ldCol = (tid & 1) * 4;

    float acc[8][8];
    #pragma unroll
    for (int i = 0; i < 8; i++)
        #pragma unroll
        for (int j = 0; j < 8; j++) acc[i][j] = 0.f;

    const float* Aptr = A + (size_t)(row0 + ldRow) * lda + z * Kc + ldCol;
    bool bValid = (col0 + ldRow) < N;
    const float* Bptr = Bw + (size_t)(col0 + ldRow) * ldb + z * Kc + ldCol;

    for (int k0 = 0; k0 < Kc; k0 += 8) {
        float4 av = *(const float4*)(Aptr + k0);
        float4 bv = bValid ? *(const float4*)(Bptr + k0) : make_float4(0.f,0.f,0.f,0.f);
        As[ldCol+0][ldRow] = av.x; As[ldCol+1][ldRow] = av.y;
        As[ldCol+2][ldRow] = av.z; As[ldCol+3][ldRow] = av.w;
        Bs[ldCol+0][ldRow] = bv.x; Bs[ldCol+1][ldRow] = bv.y;
        Bs[ldCol+2][ldRow] = bv.z; Bs[ldCol+3][ldRow] = bv.w;
        __syncthreads();
        #pragma unroll
        for (int kk = 0; kk < 8; kk++) {
            float a[8], b[8];
            *(float4*)(a)     = *(const float4*)&As[kk][ty*8];
            *(float4*)(a + 4) = *(const float4*)&As[kk][ty*8+4];
            *(float4*)(b)     = *(const float4*)&Bs[kk][tx*8];
            *(float4*)(b + 4) = *(const float4*)&Bs[kk][tx*8+4];
            #pragma unroll
            for (int i = 0; i < 8; i++)
                #pragma unroll
                for (int j = 0; j < 8; j++)
                    acc[i][j] = fmaf(a[i], b[j], acc[i][j]);
        }
        __syncthreads();
    }
    float* Cz = Cpart + (size_t)z * M * N;
    #pragma unroll
    for (int i = 0; i < 8; i++) {
        int r = row0 + ty*8 + i;
        #pragma unroll
        for (int j = 0; j < 8; j++) {
            int c = col0 + tx*8 + j;
            if (c < N) Cz[(size_t)r * N + c] = acc[i][j];
        }
    }
}

// reduce split-K partials; route dt cols to xdbl, B/C cols to transposed arrays
__global__ void reduce_splitk_T(const float* __restrict__ parts)
{
    const int total = MROWS * XDBL_W;
    int i = blockIdx.x * blockDim.x + threadIdx.x;
    if (i >= total) return;
    float v = 0.f;
    #pragma unroll
    for (int z = 0; z < KSPLIT; z++) v += parts[i + (size_t)z * total];
    int m = i / XDBL_W;
    int c = i - m * XDBL_W;
    if (c < DTRANK) {
        g_xdbl[i] = v;
    } else {
        int b = m >> 11, t = m & (SEQ - 1);
        int cc = c - DTRANK;          // 0..31
        if (cc < DSTATE) g_BT[(size_t)(b*DSTATE + cc) * SEQ + t] = v;
        else             g_CT[(size_t)(b*DSTATE + cc - DSTATE) * SEQ + t] = v;
    }
}

// ====== fused causal conv(k=4)+SiLU -> g_xc & g_xcT;  SiLU(z) -> g_zsT ======
// 32x32 (t,d) tiles; grid (DINNER/32, B_SZ*SEQ/32); 256 thr = 32x8.
__global__ void __launch_bounds__(256) conv_silu_T_kernel(
    const float* __restrict__ conv_w, const float* __restrict__ conv_b)
{
    __shared__ float xin[36][33];   // rows t0-3 .. t0+31 of xz xc-half
    __shared__ float xo [32][33];   // conv+silu output (for transpose)
    __shared__ float zt [32][33];   // silu(z) (for transpose)

    int b  = blockIdx.y >> 6;              // SEQ/32 = 64 t-tiles per batch
    int t0 = (blockIdx.y & 63) << 5;
    int d0 = blockIdx.x << 5;
    int tx = threadIdx.x & 31, ty = threadIdx.x >> 5;

    // load xc-half rows t0-3 .. t0+31 (35 rows)
    #pragma unroll
    for (int k = 0; k < 5; k++) {
        int r = ty + k * 8;
        if (r < 35) {
            int t = t0 - 3 + r;
            xin[r][tx] = (t >= 0)
                ? g_xz[(size_t)(b * SEQ + t) * (2 * DINNER) + d0 + tx] : 0.f;
        }
    }
    // load z-half rows t0 .. t0+31, apply silu
    #pragma unroll
    for (int k = 0; k < 4; k++) {
        int r = ty + k * 8;
        float v = g_xz[(size_t)(b * SEQ + t0 + r) * (2 * DINNER) + DINNER + d0 + tx];
        zt[r][tx] = v / (1.f + __expf(-v));
    }
    __syncthreads();

    int d = d0 + tx;
    float w0 = conv_w[d * DCONV + 0], w1 = conv_w[d * DCONV + 1];
    float w2 = conv_w[d * DCONV + 2], w3 = conv_w[d * DCONV + 3];
    float bs = conv_b[d];

    #pragma unroll
    for (int k = 0; k < 4; k++) {
        int r = ty + k * 8;             // output t = t0 + r uses xin rows r..r+3
        float s = bs;
        s = fmaf(w0, xin[r][tx], s);
        s = fmaf(w1, xin[r + 1][tx], s);
        s = fmaf(w2, xin[r + 2][tx], s);
        s = fmaf(w3, xin[r + 3][tx], s);
        s = s / (1.f + __expf(-s));
        g_xc[(size_t)(b * SEQ + t0 + r) * DINNER + d] = s;   // coalesced
        xo[r][tx] = s;
    }
    __syncthreads();

    // transposed writes (channel-major)
    #pragma unroll
    for (int k = 0; k < 4; k++) {
        int row = ty + k * 8;
        size_t o = (size_t)(b * DINNER + d0 + row) * SEQ + t0 + tx;
        g_xcT[o] = xo[tx][row];
        g_zsT[o] = zt[tx][row];
    }
}

// ---------------- transpose for dt only ----------------
__global__ void __launch_bounds__(256) transpose_dt_kernel()
{
    __shared__ float tile[32][33];
    int b  = blockIdx.y >> 6;
    int t0 = (blockIdx.y & 63) << 5;
    int d0 = blockIdx.x << 5;
    int tx = threadIdx.x & 31, ty = threadIdx.x >> 5;

    #pragma unroll
    for (int k = 0; k < 32; k += 8)
        tile[ty + k][tx] = g_dt[(size_t)(b*SEQ + t0 + ty + k) * DINNER + d0 + tx];
    __syncthreads();
    #pragma unroll
    for (int k = 0; k < 32; k += 8)
        g_dtT[(size_t)(b*DINNER + d0 + ty + k) * SEQ + t0 + tx] = tile[tx][ty + k];
}

// ---------------- selective scan v5: smem B/C tiles, packed stores ----------
#define UNR2 16
#define T_TILE 128
#define SPAD 132
__global__ void __launch_bounds__(256) scan_kernel(const float* __restrict__ A_log,
                                                   const float* __restrict__ Dp)
{
    __shared__ float sB[DSTATE][SPAD];
    __shared__ float sC[DSTATE][SPAD];

    int tid  = threadIdx.x;
    int lane = tid & 31;
    int warp = tid >> 5;
    int c2 = lane >> 4;
    int n  = lane & 15;
    int ch = blockIdx.x * 16 + warp * 2 + c2;
    int b  = ch >> 11;
    int d  = ch & (DINNER - 1);
    int d0 = d & ~1;

    float Ac = -__expf(__ldg(A_log + d * DSTATE + n));
    float Dd = Dp[d];
    float h  = 0.f;

    const float* dtT = g_dtT + (size_t)ch * SEQ;
    const float* xT  = g_xcT + (size_t)ch * SEQ;
    const float* zT  = g_zsT + (size_t)ch * SEQ;
    const float* BTb = g_BT  + (size_t)b * DSTATE * SEQ;
    const float* CTb = g_CT  + (size_t)b * DSTATE * SEQ;
    int srcbase = c2 << 4;

    int ldr = tid >> 5;
    int ldc = (tid & 31) * 4;

    for (int tb = 0; tb < SEQ; tb += T_TILE) {
        __syncthreads();
        #pragma unroll
        for (int rr = 0; rr < 2; rr++) {
            int r = ldr + rr * 8;
            float4 bv = *(const float4*)(BTb + (size_t)r * SEQ + tb + ldc);
            float4 cv = *(const float4*)(CTb + (size_t)r * SEQ + tb + ldc);
            *(float4*)&sB[r][ldc] = bv;
            *(float4*)&sC[r][ldc] = cv;
        }
        __syncthreads();

        for (int tt = 0; tt < T_TILE; tt += UNR2) {
            int t0 = tb + tt;
            float dt_l = __ldg(dtT + t0 + n);
            float x_l  = __ldg(xT  + t0 + n);
            float z_l  = __ldg(zT  + t0 + n);
            float pre_l = dt_l * x_l;

            float Bn[UNR2], Cn[UNR2];
            #pragma unroll
            for (int q = 0; q < UNR2; q += 4) {
                float4 bq = *(const float4*)&sB[n][tt + q];
                float4 cq = *(const float4*)&sC[n][tt + q];
                Bn[q] = bq.x; Bn[q+1] = bq.y; Bn[q+2] = bq.z; Bn[q+3] = bq.w;
                Cn[q] = cq.x; Cn[q+1] = cq.y; Cn[q+2] = cq.z; Cn[q+3] = cq.w;
            }

            float dA[UNR2];
            #pragma unroll
            for (int u = 0; u < UNR2; u++) {
                float dtu  = __shfl_sync(0xffffffffu, dt_l,  srcbase + u);
                float preu = __shfl_sync(0xffffffffu, pre_l, srcbase + u);
                Bn[u] = preu * Bn[u];
                dA[u] = __expf(dtu * Ac);
            }

            float p[UNR2];
            #pragma unroll
            for (int u = 0; u < UNR2; u++) {
                h = fmaf(dA[u], h, Bn[u]);
                p[u] = h * Cn[u];
            }

            // reduce-scatter: lane n ends with sum for timestep t0+n
            float q8[8];
            #pragma unroll
            for (int v = 0; v < 8; v++) {
                float keep = (n & 8) ? p[v + 8] : p[v];
                float send = (n & 8) ? p[v]     : p[v + 8];
                q8[v] = keep + __shfl_xor_sync(0xffffffffu, send, 8);
            }
            float q4[4];
            #pragma unroll
            for (int v = 0; v < 4; v++) {
                float keep = (n & 4) ? q8[v + 4] : q8[v];
                float send = (n & 4) ? q8[v]     : q8[v + 4];
                q4[v] = keep + __shfl_xor_sync(0xffffffffu, send, 4);
            }
            float q2[2];
            #pragma unroll
            for (int v = 0; v < 2; v++) {
                float keep = (n & 2) ? q4[v + 2] : q4[v];
                float send = (n & 2) ? q4[v]     : q4[v + 2];
                q2[v] = keep + __shfl_xor_sync(0xffffffffu, send, 2);
            }
            float keep = (n & 1) ? q2[1] : q2[0];
            float send = (n & 1) ? q2[0] : q2[1];
            float ps = keep + __shfl_xor_sync(0xffffffffu, send, 1);

            float yv = fmaf(Dd, x_l, ps) * z_l;
            float yvp = __shfl_xor_sync(0xffffffffu, yv, 16);
            if (c2 == 0) {
                __nv_bfloat16 h0 = __float2bfloat16(yv);
                __nv_bfloat16 h1 = __float2bfloat16(yvp);
                __nv_bfloat16 l0 = __float2bfloat16(yv  - __bfloat162float(h0));
                __nv_bfloat16 l1 = __float2bfloat16(yvp - __bfloat162float(h1));
                size_t m = (size_t)(b * SEQ + t0 + n);
                *(__nv_bfloat162*)(g_yh + m * DINNER + d0) = __halves2bfloat162(h0, h1);
                *(__nv_bfloat162*)(g_yl + m * DINNER + d0) = __halves2bfloat162(l0, l1);
            }
        }
    }
}

// ---------------- launch ----------------
extern "C" void kernel_launch(void* const* d_in, const int* in_sizes, int n_in,
                              void* d_out, int out_size)
{
    const float* x          = (const float*)d_in[0];
    const float* in_proj_w  = (const float*)d_in[1];
    const float* conv_w     = (const float*)d_in[2];
    const float* conv_b     = (const float*)d_in[3];
    const float* A_log      = (const float*)d_in[4];
    const float* Dp         = (const float*)d_in[5];
    const float* x_proj_w   = (const float*)d_in[6];
    const float* dt_proj_w  = (const float*)d_in[7];
    const float* dt_proj_b  = (const float*)d_in[8];
    const float* out_proj_w = (const float*)d_in[9];
    float*       out        = (float*)d_out;

    float *xz, *xc, *xdblp, *dt;
    __nv_bfloat16 *xh, *xl, *wih, *wil, *yh, *yl, *woh, *wol, *dwh, *dwl, *x64h, *x64l;
    cudaGetSymbolAddress((void**)&xz,    g_xz);
    cudaGetSymbolAddress((void**)&xc,    g_xc);
    cudaGetSymbolAddress((void**)&xdblp, g_xdblp);
    cudaGetSymbolAddress((void**)&dt,    g_dt);
    cudaGetSymbolAddress((void**)&xh,   g_xh);
    cudaGetSymbolAddress((void**)&xl,   g_xl);
    cudaGetSymbolAddress((void**)&wih,  g_wih);
    cudaGetSymbolAddress((void**)&wil,  g_wil);
    cudaGetSymbolAddress((void**)&yh,   g_yh);
    cudaGetSymbolAddress((void**)&yl,   g_yl);
    cudaGetSymbolAddress((void**)&woh,  g_woh);
    cudaGetSymbolAddress((void**)&wol,  g_wol);
    cudaGetSymbolAddress((void**)&dwh,  g_dwh);
    cudaGetSymbolAddress((void**)&dwl,  g_dwl);
    cudaGetSymbolAddress((void**)&x64h, g_x64h);
    cudaGetSymbolAddress((void**)&x64l, g_x64l);

    cudaFuncSetAttribute(hmma_gemm<0>, cudaFuncAttributeMaxDynamicSharedMemorySize,
                         HMMA_SMEM);
    cudaFuncSetAttribute(hmma_gemm<1>, cudaFuncAttributeMaxDynamicSharedMemorySize,
                         HMMA_SMEM);

    // 0) bf16 hi/lo splits
    split_kernel<<<(MROWS*DMODEL + 255)/256, 256>>>(x, xh, xl, MROWS*DMODEL);
    split_kernel<<<(2*DINNER*DMODEL + 255)/256, 256>>>(in_proj_w, wih, wil, 2*DINNER*DMODEL);
    split_kernel<<<(DMODEL*DINNER + 255)/256, 256>>>(out_proj_w, woh, wol, DMODEL*DINNER);
    split_kernel<<<(DINNER*DTRANK + 255)/256, 256>>>(dt_proj_w, dwh, dwl, DINNER*DTRANK);

    // 1) xz = x @ in_proj_w^T  [4096,4096] K=1024
    hmma_gemm<0><<<dim3(32, 32), 256, HMMA_SMEM>>>(xh, xl, wih, wil, xz, nullptr,
                                                   DMODEL, 2*DINNER);

    // 2) fused conv+silu -> xc & xcT;  silu(z) -> zsT
    conv_silu_T_kernel<<<dim3(64, 128), 256>>>(conv_w, conv_b);

    // 3) x_dbl = xc @ x_proj_w^T — split-K x8 + routed reduce (B,C transposed)
    sgemm_splitk<<<dim3(1, 32, KSPLIT), 256>>>(xc, x_proj_w, xdblp,
                                               MROWS, XDBL_W, DINNER/KSPLIT,
                                               DINNER, DINNER);
    reduce_splitk_T<<<(MROWS*XDBL_W + 255)/256, 256>>>(xdblp);

    // 3b) split xdbl[:, :64] to packed bf16 hi/lo
    split_x64_kernel<<<(MROWS*DTRANK + 255)/256, 256>>>();

    // 4) dt = softplus(xdbl64 @ dt_proj_w^T + b)  [4096,2048] K=64 — HMMA
    hmma_gemm<1><<<dim3(16, 32), 256, HMMA_SMEM>>>(x64h, x64l, dwh, dwl, dt, dt_proj_b,
                                                   DTRANK, DINNER);

    // 4b) transpose dt -> dtT
    transpose_dt_kernel<<<dim3(64, 128), 256>>>();

    // 5) selective scan v5
    scan_kernel<<<256, 256>>>(A_log, Dp);

    // 6) out = y @ out_proj_w^T  [4096,1024] K=2048
    hmma_gemm<0><<<dim3(8, 32), 256, HMMA_SMEM>>>(yh, yl, woh, wol, out, nullptr,
                                                  DINNER, DMODEL);
}